// round 6
// baseline (speedup 1.0000x reference)
#include <cuda_runtime.h>
#include <cuda_bf16.h>

#define D 128
#define MAXN 100000
#define MAXE 1000000
#define BM 64
#define KC 32

// -------- device scratch (allocation-free rule: static __device__ arrays) --------
__device__ __align__(16) float g_h[(size_t)MAXN * D];     // u = (x @ W) * dinv  (pre-scaled)
__device__ __align__(16) float g_agg[(size_t)MAXN * D];   // selfloop + b + res, then + scatter
__device__ __align__(16) float g_dinv[MAXN];              // deg^{-1/2}
__device__ __align__(16) float g_sum[D];
__device__ __align__(16) float g_sumsq[D];
__device__ __align__(16) float g_scale[D];
__device__ __align__(16) float g_shift[D];
__device__ int g_cnt[MAXN];        // in-degree histogram (excl. self-loop)
__device__ int g_roff[MAXN + 1];   // CSR row offsets (by dst)
__device__ int g_wcur[MAXN];       // fill cursors
__device__ int g_srcs[MAXE];       // CSR column (src) indices
__device__ int g_is64;             // edge_index dtype flag

__device__ __forceinline__ int ld_idx(const int* __restrict__ ei32, size_t pos, int is64) {
    return is64 ? ei32[pos << 1] : ei32[pos];
}

// -------- K0: zero histogram + BN sums, init dtype flag --------
__global__ void k_init(int N) {
    int i = blockIdx.x * blockDim.x + threadIdx.x;
    if (i < N) g_cnt[i] = 0;
    if (i < D) { g_sum[i] = 0.0f; g_sumsq[i] = 0.0f; }
    if (i == 0) g_is64 = 1;
}

// -------- K0b: detect edge_index dtype --------
__global__ void k_detect(const int* __restrict__ ei32, int E) {
    int i = blockIdx.x * blockDim.x + threadIdx.x;
    if (i < E && i < 1024) {
        if (ei32[2 * i + 1] != 0) g_is64 = 0;   // racy single-value write, benign
    }
}

// -------- K1: in-degree histogram over dst --------
__global__ void k_hist(const int* __restrict__ ei32, int E) {
    int e = blockIdx.x * blockDim.x + threadIdx.x;
    if (e >= E) return;
    int is64 = g_is64;
    int d = ld_idx(ei32, (size_t)E + e, is64);
    atomicAdd(&g_cnt[d], 1);
}

// -------- K2: single-block exclusive scan over cnt -> roff, wcur; dinv = rsqrt(cnt+1) --------
__global__ void __launch_bounds__(1024) k_scan(int N) {
    __shared__ int part[1024];
    int t = threadIdx.x;
    int chunk = (N + 1023) / 1024;
    int lo = t * chunk, hi = min(lo + chunk, N);
    int s = 0;
    for (int i = lo; i < hi; i++) s += g_cnt[i];
    part[t] = s;
    __syncthreads();
    // Hillis-Steele inclusive scan on partials
    for (int off = 1; off < 1024; off <<= 1) {
        int v = (t >= off) ? part[t - off] : 0;
        __syncthreads();
        part[t] += v;
        __syncthreads();
    }
    int run = (t > 0) ? part[t - 1] : 0;   // exclusive prefix of this thread's chunk
    for (int i = lo; i < hi; i++) {
        int c = g_cnt[i];
        g_roff[i] = run;
        g_wcur[i] = run;
        g_dinv[i] = rsqrtf((float)c + 1.0f);
        run += c;
    }
    if (t == 1023) g_roff[N] = run;
}

// -------- K3: fill CSR src lists (order nondeterministic; sums tolerance-safe) --------
__global__ void k_fill(const int* __restrict__ ei32, int E) {
    int e = blockIdx.x * blockDim.x + threadIdx.x;
    if (e >= E) return;
    int is64 = g_is64;
    int s = ld_idx(ei32, (size_t)e, is64);
    int d = ld_idx(ei32, (size_t)E + e, is64);
    int pos = atomicAdd(&g_wcur[d], 1);
    g_srcs[pos] = s;
}

// -------- K4: fused dual GEMM + epilogue --------
// u = (x@W)*dinv ;  agg = u*dinv + b + relu(x@res_W + res_b)
__global__ void __launch_bounds__(256) k_gemm(
    const float* __restrict__ x, const float* __restrict__ W,
    const float* __restrict__ b, const float* __restrict__ rW,
    const float* __restrict__ rb, int N)
{
    __shared__ float xs[BM][KC + 1];
    __shared__ float Ws[KC][D];
    __shared__ float Rs[KC][D];

    int tid = threadIdx.x;
    int row0 = blockIdx.x * BM;
    int tx = tid & 15;
    int ty = tid >> 4;

    float aW[4][8], aR[4][8];
    #pragma unroll
    for (int r = 0; r < 4; r++)
        #pragma unroll
        for (int c = 0; c < 8; c++) { aW[r][c] = 0.f; aR[r][c] = 0.f; }

    const float4* x4 = (const float4*)x;
    const float4* W4 = (const float4*)W;
    const float4* R4 = (const float4*)rW;

    for (int k0 = 0; k0 < D; k0 += KC) {
        __syncthreads();
        #pragma unroll
        for (int i = 0; i < 2; i++) {
            int lin = tid + i * 256;
            int r = lin >> 3, c4 = lin & 7;
            int grow = row0 + r;
            float4 v = (grow < N) ? x4[(size_t)grow * 32 + (k0 >> 2) + c4]
                                  : make_float4(0.f, 0.f, 0.f, 0.f);
            float* p = &xs[r][c4 * 4];
            p[0] = v.x; p[1] = v.y; p[2] = v.z; p[3] = v.w;
        }
        #pragma unroll
        for (int i = 0; i < 4; i++) {
            int lin = tid + i * 256;
            int kr = lin >> 5, c4 = lin & 31;
            ((float4*)&Ws[kr][0])[c4] = W4[(size_t)(k0 + kr) * 32 + c4];
            ((float4*)&Rs[kr][0])[c4] = R4[(size_t)(k0 + kr) * 32 + c4];
        }
        __syncthreads();

        #pragma unroll 8
        for (int kk = 0; kk < KC; kk++) {
            float a[4];
            a[0] = xs[ty * 4 + 0][kk];
            a[1] = xs[ty * 4 + 1][kk];
            a[2] = xs[ty * 4 + 2][kk];
            a[3] = xs[ty * 4 + 3][kk];
            float4 w0 = *(const float4*)&Ws[kk][tx * 8];
            float4 w1 = *(const float4*)&Ws[kk][tx * 8 + 4];
            float4 r0 = *(const float4*)&Rs[kk][tx * 8];
            float4 r1 = *(const float4*)&Rs[kk][tx * 8 + 4];
            #pragma unroll
            for (int r = 0; r < 4; r++) {
                aW[r][0] += a[r] * w0.x; aW[r][1] += a[r] * w0.y;
                aW[r][2] += a[r] * w0.z; aW[r][3] += a[r] * w0.w;
                aW[r][4] += a[r] * w1.x; aW[r][5] += a[r] * w1.y;
                aW[r][6] += a[r] * w1.z; aW[r][7] += a[r] * w1.w;
                aR[r][0] += a[r] * r0.x; aR[r][1] += a[r] * r0.y;
                aR[r][2] += a[r] * r0.z; aR[r][3] += a[r] * r0.w;
                aR[r][4] += a[r] * r1.x; aR[r][5] += a[r] * r1.y;
                aR[r][6] += a[r] * r1.z; aR[r][7] += a[r] * r1.w;
            }
        }
    }

    #pragma unroll
    for (int r = 0; r < 4; r++) {
        int grow = row0 + ty * 4 + r;
        if (grow >= N) continue;
        float di = g_dinv[grow];
        #pragma unroll
        for (int c4 = 0; c4 < 2; c4++) {
            int col = tx * 8 + c4 * 4;
            float4 bb  = *(const float4*)(b + col);
            float4 rbb = *(const float4*)(rb + col);
            float4 uv;   // u = h * dinv
            uv.x = aW[r][c4 * 4 + 0] * di; uv.y = aW[r][c4 * 4 + 1] * di;
            uv.z = aW[r][c4 * 4 + 2] * di; uv.w = aW[r][c4 * 4 + 3] * di;
            *(float4*)(g_h + (size_t)grow * D + col) = uv;
            float4 av;   // self-loop u*dinv + b + relu(res)
            av.x = uv.x * di + bb.x + fmaxf(aR[r][c4 * 4 + 0] + rbb.x, 0.f);
            av.y = uv.y * di + bb.y + fmaxf(aR[r][c4 * 4 + 1] + rbb.y, 0.f);
            av.z = uv.z * di + bb.z + fmaxf(aR[r][c4 * 4 + 2] + rbb.z, 0.f);
            av.w = uv.w * di + bb.w + fmaxf(aR[r][c4 * 4 + 3] + rbb.w, 0.f);
            *(float4*)(g_agg + (size_t)grow * D + col) = av;
        }
    }
}

// -------- K5: CSR aggregate. Warp per dst node, no atomics --------
__global__ void k_agg(int N) {
    int gt = blockIdx.x * blockDim.x + threadIdx.x;
    int d = gt >> 5;
    int lane = threadIdx.x & 31;
    if (d >= N) return;
    int beg = g_roff[d], end = g_roff[d + 1];
    if (beg == end) return;
    float4 acc = make_float4(0.f, 0.f, 0.f, 0.f);
    for (int j = beg; j < end; j++) {
        int s = g_srcs[j];                                 // broadcast load
        float4 u = *(const float4*)(g_h + (size_t)s * D + lane * 4);
        acc.x += u.x; acc.y += u.y; acc.z += u.z; acc.w += u.w;
    }
    float di = g_dinv[d];
    float4* ap = (float4*)(g_agg + (size_t)d * D + lane * 4);
    float4 v = *ap;
    v.x += acc.x * di; v.y += acc.y * di;
    v.z += acc.z * di; v.w += acc.w * di;
    *ap = v;
}

// -------- K6: BN column sums --------
__global__ void k_bnsum(int N) {
    int col = threadIdx.x;   // 128 threads
    float s = 0.f, sq = 0.f;
    for (int r = blockIdx.x; r < N; r += gridDim.x) {
        float v = g_agg[(size_t)r * D + col];
        s += v; sq += v * v;
    }
    atomicAdd(&g_sum[col], s);
    atomicAdd(&g_sumsq[col], sq);
}

// -------- K7: finalize BN scale/shift --------
__global__ void k_bnfin(const float* __restrict__ gamma,
                        const float* __restrict__ beta, int N) {
    int c = threadIdx.x;
    float inv_n = 1.0f / (float)N;
    float mean = g_sum[c] * inv_n;
    float var = fmaxf(g_sumsq[c] * inv_n - mean * mean, 0.0f);
    float sc = rsqrtf(var + 1e-5f) * gamma[c];
    g_scale[c] = sc;
    g_shift[c] = beta[c] - mean * sc;
}

// -------- K8: normalize to output --------
__global__ void k_norm(float* __restrict__ out, int N) {
    int idx = blockIdx.x * blockDim.x + threadIdx.x;
    int total = N * (D / 4);
    if (idx >= total) return;
    int colb = (idx & 31) * 4;
    float4 v  = ((const float4*)g_agg)[idx];
    float4 sc = *(const float4*)(g_scale + colb);
    float4 sh = *(const float4*)(g_shift + colb);
    float4 o;
    o.x = v.x * sc.x + sh.x;
    o.y = v.y * sc.y + sh.y;
    o.z = v.z * sc.z + sh.z;
    o.w = v.w * sc.w + sh.w;
    ((float4*)out)[idx] = o;
}

extern "C" void kernel_launch(void* const* d_in, const int* in_sizes, int n_in,
                              void* d_out, int out_size) {
    const float* x     = (const float*)d_in[0];
    const int*   ei32  = (const int*)d_in[1];     // int32 OR int64 (auto-detected)
    const float* W     = (const float*)d_in[2];
    const float* b     = (const float*)d_in[3];
    const float* rW    = (const float*)d_in[4];
    const float* rb    = (const float*)d_in[5];
    const float* gamma = (const float*)d_in[6];
    const float* beta  = (const float*)d_in[7];
    float* out = (float*)d_out;

    int N = in_sizes[0] / D;
    int E = in_sizes[1] / 2;

    k_init<<<(N + 255) / 256, 256>>>(N);
    k_detect<<<4, 256>>>(ei32, E);
    k_hist<<<(E + 255) / 256, 256>>>(ei32, E);
    k_scan<<<1, 1024>>>(N);
    k_fill<<<(E + 255) / 256, 256>>>(ei32, E);
    k_gemm<<<(N + BM - 1) / BM, 256>>>(x, W, b, rW, rb, N);
    k_agg<<<(N * 32 + 255) / 256, 256>>>(N);
    k_bnsum<<<512, 128>>>(N);
    k_bnfin<<<1, 128>>>(gamma, beta, N);
    k_norm<<<(N * (D / 4) + 255) / 256, 256>>>(out, N);
}

// round 7
// speedup vs baseline: 1.5503x; 1.5503x over previous
#include <cuda_runtime.h>
#include <cuda_bf16.h>

#define D 128
#define MAXN 100000
#define MAXE 1000000
#define BM 64
#define KC 32
#define SCAN_B 256
#define MAXBLK ((MAXN + SCAN_B - 1) / SCAN_B)

// -------- device scratch (allocation-free rule: static __device__ arrays) --------
__device__ __align__(16) float g_h[(size_t)MAXN * D];     // u = (x @ W) * dinv  (pre-scaled)
__device__ __align__(16) float g_agg[(size_t)MAXN * D];   // selfloop + b + res, then + scatter
__device__ __align__(16) float g_dinv[MAXN];              // deg^{-1/2}
__device__ __align__(16) float g_sum[D];
__device__ __align__(16) float g_sumsq[D];
__device__ __align__(16) float g_scale[D];
__device__ __align__(16) float g_shift[D];
__device__ int g_cnt[MAXN];        // in-degree histogram (excl. self-loop)
__device__ int g_roff[MAXN + 1];   // CSR row offsets (by dst)
__device__ int g_wcur[MAXN];       // fill cursors
__device__ int g_srcs[MAXE];       // CSR column (src) indices
__device__ int g_bsum[MAXBLK];     // per-block count sums -> exclusive offsets
__device__ int g_is64;             // edge_index dtype flag

__device__ __forceinline__ int ld_idx(const int* __restrict__ ei32, size_t pos, int is64) {
    return is64 ? ei32[pos << 1] : ei32[pos];
}

// -------- K0: zero histogram + BN sums, init dtype flag --------
__global__ void k_init(int N) {
    int i = blockIdx.x * blockDim.x + threadIdx.x;
    if (i < N) g_cnt[i] = 0;
    if (i < D) { g_sum[i] = 0.0f; g_sumsq[i] = 0.0f; }
    if (i == 0) g_is64 = 1;
}

// -------- K0b: detect edge_index dtype --------
__global__ void k_detect(const int* __restrict__ ei32, int E) {
    int i = blockIdx.x * blockDim.x + threadIdx.x;
    if (i < E && i < 1024) {
        if (ei32[2 * i + 1] != 0) g_is64 = 0;   // racy single-value write, benign
    }
}

// -------- K1: in-degree histogram over dst --------
__global__ void k_hist(const int* __restrict__ ei32, int E) {
    int e = blockIdx.x * blockDim.x + threadIdx.x;
    if (e >= E) return;
    int is64 = g_is64;
    int d = ld_idx(ei32, (size_t)E + e, is64);
    atomicAdd(&g_cnt[d], 1);
}

// -------- K2a: per-block sums of cnt --------
__global__ void __launch_bounds__(SCAN_B) k_scan1(int N) {
    __shared__ int red[SCAN_B / 32];
    int i = blockIdx.x * SCAN_B + threadIdx.x;
    int v = (i < N) ? g_cnt[i] : 0;
    #pragma unroll
    for (int o = 16; o > 0; o >>= 1) v += __shfl_down_sync(0xffffffff, v, o);
    int warp = threadIdx.x >> 5, lane = threadIdx.x & 31;
    if (lane == 0) red[warp] = v;
    __syncthreads();
    if (warp == 0) {
        int s = (lane < SCAN_B / 32) ? red[lane] : 0;
        #pragma unroll
        for (int o = 4; o > 0; o >>= 1) s += __shfl_down_sync(0xffffffff, s, o);
        if (lane == 0) g_bsum[blockIdx.x] = s;
    }
}

// -------- K2b: single block: exclusive scan of block sums (nblk <= 1024) --------
__global__ void __launch_bounds__(1024) k_scan2(int nblk, int N) {
    __shared__ int sh[1024];
    int t = threadIdx.x;
    int v = (t < nblk) ? g_bsum[t] : 0;
    sh[t] = v;
    __syncthreads();
    for (int off = 1; off < 1024; off <<= 1) {
        int u = (t >= off) ? sh[t - off] : 0;
        __syncthreads();
        sh[t] += u;
        __syncthreads();
    }
    if (t < nblk) g_bsum[t] = sh[t] - v;      // exclusive
    if (t == 0) g_roff[N] = sh[1023];         // total E
}

// -------- K2c: in-block exclusive scan + block offset -> roff/wcur/dinv --------
__global__ void __launch_bounds__(SCAN_B) k_scan3(int N) {
    __shared__ int wsum[SCAN_B / 32];
    int i = blockIdx.x * SCAN_B + threadIdx.x;
    int c = (i < N) ? g_cnt[i] : 0;
    int lane = threadIdx.x & 31, warp = threadIdx.x >> 5;
    // warp inclusive scan
    int s = c;
    #pragma unroll
    for (int o = 1; o < 32; o <<= 1) {
        int u = __shfl_up_sync(0xffffffff, s, o);
        if (lane >= o) s += u;
    }
    if (lane == 31) wsum[warp] = s;
    __syncthreads();
    if (warp == 0) {
        int w = (lane < SCAN_B / 32) ? wsum[lane] : 0;
        #pragma unroll
        for (int o = 1; o < SCAN_B / 32; o <<= 1) {
            int u = __shfl_up_sync(0xffffffff, w, o);
            if (lane >= o) w += u;
        }
        if (lane < SCAN_B / 32) wsum[lane] = w;
    }
    __syncthreads();
    int excl = s - c + (warp > 0 ? wsum[warp - 1] : 0) + g_bsum[blockIdx.x];
    if (i < N) {
        g_roff[i] = excl;
        g_wcur[i] = excl;
        g_dinv[i] = rsqrtf((float)c + 1.0f);
    }
}

// -------- K3: fill CSR src lists (order nondeterministic; sums tolerance-safe) --------
__global__ void k_fill(const int* __restrict__ ei32, int E) {
    int e = blockIdx.x * blockDim.x + threadIdx.x;
    if (e >= E) return;
    int is64 = g_is64;
    int s = ld_idx(ei32, (size_t)e, is64);
    int d = ld_idx(ei32, (size_t)E + e, is64);
    int pos = atomicAdd(&g_wcur[d], 1);
    g_srcs[pos] = s;
}

// -------- K4: fused dual GEMM + epilogue --------
// u = (x@W)*dinv ;  agg = u*dinv + b + relu(x@res_W + res_b)
__global__ void __launch_bounds__(256) k_gemm(
    const float* __restrict__ x, const float* __restrict__ W,
    const float* __restrict__ b, const float* __restrict__ rW,
    const float* __restrict__ rb, int N)
{
    __shared__ float xs[BM][KC + 1];
    __shared__ float Ws[KC][D];
    __shared__ float Rs[KC][D];

    int tid = threadIdx.x;
    int row0 = blockIdx.x * BM;
    int tx = tid & 15;
    int ty = tid >> 4;

    float aW[4][8], aR[4][8];
    #pragma unroll
    for (int r = 0; r < 4; r++)
        #pragma unroll
        for (int c = 0; c < 8; c++) { aW[r][c] = 0.f; aR[r][c] = 0.f; }

    const float4* x4 = (const float4*)x;
    const float4* W4 = (const float4*)W;
    const float4* R4 = (const float4*)rW;

    for (int k0 = 0; k0 < D; k0 += KC) {
        __syncthreads();
        #pragma unroll
        for (int i = 0; i < 2; i++) {
            int lin = tid + i * 256;
            int r = lin >> 3, c4 = lin & 7;
            int grow = row0 + r;
            float4 v = (grow < N) ? x4[(size_t)grow * 32 + (k0 >> 2) + c4]
                                  : make_float4(0.f, 0.f, 0.f, 0.f);
            float* p = &xs[r][c4 * 4];
            p[0] = v.x; p[1] = v.y; p[2] = v.z; p[3] = v.w;
        }
        #pragma unroll
        for (int i = 0; i < 4; i++) {
            int lin = tid + i * 256;
            int kr = lin >> 5, c4 = lin & 31;
            ((float4*)&Ws[kr][0])[c4] = W4[(size_t)(k0 + kr) * 32 + c4];
            ((float4*)&Rs[kr][0])[c4] = R4[(size_t)(k0 + kr) * 32 + c4];
        }
        __syncthreads();

        #pragma unroll 8
        for (int kk = 0; kk < KC; kk++) {
            float a[4];
            a[0] = xs[ty * 4 + 0][kk];
            a[1] = xs[ty * 4 + 1][kk];
            a[2] = xs[ty * 4 + 2][kk];
            a[3] = xs[ty * 4 + 3][kk];
            float4 w0 = *(const float4*)&Ws[kk][tx * 8];
            float4 w1 = *(const float4*)&Ws[kk][tx * 8 + 4];
            float4 r0 = *(const float4*)&Rs[kk][tx * 8];
            float4 r1 = *(const float4*)&Rs[kk][tx * 8 + 4];
            #pragma unroll
            for (int r = 0; r < 4; r++) {
                aW[r][0] += a[r] * w0.x; aW[r][1] += a[r] * w0.y;
                aW[r][2] += a[r] * w0.z; aW[r][3] += a[r] * w0.w;
                aW[r][4] += a[r] * w1.x; aW[r][5] += a[r] * w1.y;
                aW[r][6] += a[r] * w1.z; aW[r][7] += a[r] * w1.w;
                aR[r][0] += a[r] * r0.x; aR[r][1] += a[r] * r0.y;
                aR[r][2] += a[r] * r0.z; aR[r][3] += a[r] * r0.w;
                aR[r][4] += a[r] * r1.x; aR[r][5] += a[r] * r1.y;
                aR[r][6] += a[r] * r1.z; aR[r][7] += a[r] * r1.w;
            }
        }
    }

    #pragma unroll
    for (int r = 0; r < 4; r++) {
        int grow = row0 + ty * 4 + r;
        if (grow >= N) continue;
        float di = g_dinv[grow];
        #pragma unroll
        for (int c4 = 0; c4 < 2; c4++) {
            int col = tx * 8 + c4 * 4;
            float4 bb  = *(const float4*)(b + col);
            float4 rbb = *(const float4*)(rb + col);
            float4 uv;   // u = h * dinv
            uv.x = aW[r][c4 * 4 + 0] * di; uv.y = aW[r][c4 * 4 + 1] * di;
            uv.z = aW[r][c4 * 4 + 2] * di; uv.w = aW[r][c4 * 4 + 3] * di;
            *(float4*)(g_h + (size_t)grow * D + col) = uv;
            float4 av;   // self-loop u*dinv + b + relu(res)
            av.x = uv.x * di + bb.x + fmaxf(aR[r][c4 * 4 + 0] + rbb.x, 0.f);
            av.y = uv.y * di + bb.y + fmaxf(aR[r][c4 * 4 + 1] + rbb.y, 0.f);
            av.z = uv.z * di + bb.z + fmaxf(aR[r][c4 * 4 + 2] + rbb.z, 0.f);
            av.w = uv.w * di + bb.w + fmaxf(aR[r][c4 * 4 + 3] + rbb.w, 0.f);
            *(float4*)(g_agg + (size_t)grow * D + col) = av;
        }
    }
}

// -------- K5: CSR aggregate. Warp per dst node, no atomics --------
__global__ void k_agg(int N) {
    int gt = blockIdx.x * blockDim.x + threadIdx.x;
    int d = gt >> 5;
    int lane = threadIdx.x & 31;
    if (d >= N) return;
    int beg = g_roff[d], end = g_roff[d + 1];
    if (beg == end) return;
    float4 acc = make_float4(0.f, 0.f, 0.f, 0.f);
    for (int j = beg; j < end; j++) {
        int s = g_srcs[j];                                 // broadcast load
        float4 u = *(const float4*)(g_h + (size_t)s * D + lane * 4);
        acc.x += u.x; acc.y += u.y; acc.z += u.z; acc.w += u.w;
    }
    float di = g_dinv[d];
    float4* ap = (float4*)(g_agg + (size_t)d * D + lane * 4);
    float4 v = *ap;
    v.x += acc.x * di; v.y += acc.y * di;
    v.z += acc.z * di; v.w += acc.w * di;
    *ap = v;
}

// -------- K6: BN column sums --------
__global__ void k_bnsum(int N) {
    int col = threadIdx.x;   // 128 threads
    float s = 0.f, sq = 0.f;
    for (int r = blockIdx.x; r < N; r += gridDim.x) {
        float v = g_agg[(size_t)r * D + col];
        s += v; sq += v * v;
    }
    atomicAdd(&g_sum[col], s);
    atomicAdd(&g_sumsq[col], sq);
}

// -------- K7: finalize BN scale/shift --------
__global__ void k_bnfin(const float* __restrict__ gamma,
                        const float* __restrict__ beta, int N) {
    int c = threadIdx.x;
    float inv_n = 1.0f / (float)N;
    float mean = g_sum[c] * inv_n;
    float var = fmaxf(g_sumsq[c] * inv_n - mean * mean, 0.0f);
    float sc = rsqrtf(var + 1e-5f) * gamma[c];
    g_scale[c] = sc;
    g_shift[c] = beta[c] - mean * sc;
}

// -------- K8: normalize to output --------
__global__ void k_norm(float* __restrict__ out, int N) {
    int idx = blockIdx.x * blockDim.x + threadIdx.x;
    int total = N * (D / 4);
    if (idx >= total) return;
    int colb = (idx & 31) * 4;
    float4 v  = ((const float4*)g_agg)[idx];
    float4 sc = *(const float4*)(g_scale + colb);
    float4 sh = *(const float4*)(g_shift + colb);
    float4 o;
    o.x = v.x * sc.x + sh.x;
    o.y = v.y * sc.y + sh.y;
    o.z = v.z * sc.z + sh.z;
    o.w = v.w * sc.w + sh.w;
    ((float4*)out)[idx] = o;
}

extern "C" void kernel_launch(void* const* d_in, const int* in_sizes, int n_in,
                              void* d_out, int out_size) {
    const float* x     = (const float*)d_in[0];
    const int*   ei32  = (const int*)d_in[1];     // int32 OR int64 (auto-detected)
    const float* W     = (const float*)d_in[2];
    const float* b     = (const float*)d_in[3];
    const float* rW    = (const float*)d_in[4];
    const float* rb    = (const float*)d_in[5];
    const float* gamma = (const float*)d_in[6];
    const float* beta  = (const float*)d_in[7];
    float* out = (float*)d_out;

    int N = in_sizes[0] / D;
    int E = in_sizes[1] / 2;
    int nblk = (N + SCAN_B - 1) / SCAN_B;     // 391 for N=100000

    k_init<<<(N + 255) / 256, 256>>>(N);
    k_detect<<<4, 256>>>(ei32, E);
    k_hist<<<(E + 255) / 256, 256>>>(ei32, E);
    k_scan1<<<nblk, SCAN_B>>>(N);
    k_scan2<<<1, 1024>>>(nblk, N);
    k_scan3<<<nblk, SCAN_B>>>(N);
    k_fill<<<(E + 255) / 256, 256>>>(ei32, E);
    k_gemm<<<(N + BM - 1) / BM, 256>>>(x, W, b, rW, rb, N);
    k_agg<<<(N * 32 + 255) / 256, 256>>>(N);
    k_bnsum<<<512, 128>>>(N);
    k_bnfin<<<1, 128>>>(gamma, beta, N);
    k_norm<<<(N * (D / 4) + 255) / 256, 256>>>(out, N);
}

// round 9
// speedup vs baseline: 2.3046x; 1.4865x over previous
#include <cuda_runtime.h>
#include <cuda_bf16.h>
#include <cstdint>

#define D 128
#define MAXN 100000
#define MAXE 1000000
#define SCAN_B 256
#define MAXBLK ((MAXN + SCAN_B - 1) / SCAN_B)
#define BKW 68                 // B row stride in 32-bit words (64 data + 4 pad)

// ---------------- device scratch ----------------
__device__ __align__(16) float g_h[(size_t)MAXN * D];     // u = (x@W)*dinv
__device__ __align__(16) float g_agg[(size_t)MAXN * D];   // selfloop + b + res (+ scatter)
__device__ __align__(16) float g_dinv[MAXN];
__device__ __align__(16) float g_sum[D];
__device__ __align__(16) float g_sumsq[D];
__device__ __align__(16) float g_scale[D];
__device__ __align__(16) float g_shift[D];
__device__ int g_cnt[MAXN];
__device__ int g_roff[MAXN + 1];
__device__ int g_wcur[MAXN];
__device__ int g_srcs[MAXE];
__device__ int g_bsum[MAXBLK];
__device__ int g_is64;
// B operand images: [n=256][kword=68] bf16x2 words; n<128 -> W col n, else res_W col n-128
__device__ __align__(16) uint32_t g_Bw_hi[256 * BKW];
__device__ __align__(16) uint32_t g_Bw_lo[256 * BKW];

__device__ __forceinline__ int ld_idx(const int* __restrict__ ei32, size_t pos, int is64) {
    return is64 ? ei32[pos << 1] : ei32[pos];
}
__device__ __forceinline__ uint32_t pack2(float a, float b) {
    __nv_bfloat162 t = __floats2bfloat162_rn(a, b);
    return *reinterpret_cast<uint32_t*>(&t);
}
__device__ __forceinline__ float bf16_hi(float v) {
    return __bfloat162float(__float2bfloat16(v));
}
__device__ __forceinline__ void mma_bf16(float* c, const uint32_t* a, uint32_t b0, uint32_t b1) {
    asm volatile(
        "mma.sync.aligned.m16n8k16.row.col.f32.bf16.bf16.f32 "
        "{%0,%1,%2,%3}, {%4,%5,%6,%7}, {%8,%9}, {%0,%1,%2,%3};"
        : "+f"(c[0]), "+f"(c[1]), "+f"(c[2]), "+f"(c[3])
        : "r"(a[0]), "r"(a[1]), "r"(a[2]), "r"(a[3]), "r"(b0), "r"(b1));
}

// ---------------- K0: init ----------------
__global__ void k_init(int N) {
    int i = blockIdx.x * blockDim.x + threadIdx.x;
    if (i < N) g_cnt[i] = 0;
    if (i < D) { g_sum[i] = 0.0f; g_sumsq[i] = 0.0f; }
    if (i == 0) g_is64 = 1;
}

__global__ void k_detect(const int* __restrict__ ei32, int E) {
    int i = blockIdx.x * blockDim.x + threadIdx.x;
    if (i < E && i < 1024) {
        if (ei32[2 * i + 1] != 0) g_is64 = 0;
    }
}

// ---------------- K_prep: build hi/lo bf16x2 B images ----------------
__global__ void k_prep(const float* __restrict__ W, const float* __restrict__ rW) {
    int t = blockIdx.x * blockDim.x + threadIdx.x;   // 16384 threads
    if (t >= 256 * 64) return;
    int n = t >> 6, kw = t & 63;
    const float* src = (n < 128) ? W : rW;
    int col = (n < 128) ? n : n - 128;
    float v0 = src[(size_t)(2 * kw) * D + col];
    float v1 = src[(size_t)(2 * kw + 1) * D + col];
    float h0 = bf16_hi(v0), h1 = bf16_hi(v1);
    g_Bw_hi[n * BKW + kw] = pack2(v0, v1);           // rn-rounded hi parts
    g_Bw_lo[n * BKW + kw] = pack2(v0 - h0, v1 - h1);
    if (kw < 4) { g_Bw_hi[n * BKW + 64 + kw] = 0; g_Bw_lo[n * BKW + 64 + kw] = 0; }
}

// ---------------- CSR build ----------------
__global__ void k_hist(const int* __restrict__ ei32, int E) {
    int e = blockIdx.x * blockDim.x + threadIdx.x;
    if (e >= E) return;
    int is64 = g_is64;
    atomicAdd(&g_cnt[ld_idx(ei32, (size_t)E + e, is64)], 1);
}

__global__ void __launch_bounds__(SCAN_B) k_scan1(int N) {
    __shared__ int red[SCAN_B / 32];
    int i = blockIdx.x * SCAN_B + threadIdx.x;
    int v = (i < N) ? g_cnt[i] : 0;
    #pragma unroll
    for (int o = 16; o > 0; o >>= 1) v += __shfl_down_sync(0xffffffff, v, o);
    int warp = threadIdx.x >> 5, lane = threadIdx.x & 31;
    if (lane == 0) red[warp] = v;
    __syncthreads();
    if (warp == 0) {
        int s = (lane < SCAN_B / 32) ? red[lane] : 0;
        #pragma unroll
        for (int o = 4; o > 0; o >>= 1) s += __shfl_down_sync(0xffffffff, s, o);
        if (lane == 0) g_bsum[blockIdx.x] = s;
    }
}

__global__ void __launch_bounds__(1024) k_scan2(int nblk, int N) {
    __shared__ int sh[1024];
    int t = threadIdx.x;
    int v = (t < nblk) ? g_bsum[t] : 0;
    sh[t] = v;
    __syncthreads();
    for (int off = 1; off < 1024; off <<= 1) {
        int u = (t >= off) ? sh[t - off] : 0;
        __syncthreads();
        sh[t] += u;
        __syncthreads();
    }
    if (t < nblk) g_bsum[t] = sh[t] - v;
    if (t == 0) g_roff[N] = sh[1023];
}

__global__ void __launch_bounds__(SCAN_B) k_scan3(int N) {
    __shared__ int wsum[SCAN_B / 32];
    int i = blockIdx.x * SCAN_B + threadIdx.x;
    int c = (i < N) ? g_cnt[i] : 0;
    int lane = threadIdx.x & 31, warp = threadIdx.x >> 5;
    int s = c;
    #pragma unroll
    for (int o = 1; o < 32; o <<= 1) {
        int u = __shfl_up_sync(0xffffffff, s, o);
        if (lane >= o) s += u;
    }
    if (lane == 31) wsum[warp] = s;
    __syncthreads();
    if (warp == 0) {
        int w = (lane < SCAN_B / 32) ? wsum[lane] : 0;
        #pragma unroll
        for (int o = 1; o < SCAN_B / 32; o <<= 1) {
            int u = __shfl_up_sync(0xffffffff, w, o);
            if (lane >= o) w += u;
        }
        if (lane < SCAN_B / 32) wsum[lane] = w;
    }
    __syncthreads();
    int excl = s - c + (warp > 0 ? wsum[warp - 1] : 0) + g_bsum[blockIdx.x];
    if (i < N) {
        g_roff[i] = excl;
        g_wcur[i] = excl;
        g_dinv[i] = rsqrtf((float)c + 1.0f);
    }
}

__global__ void k_fill(const int* __restrict__ ei32, int E) {
    int e = blockIdx.x * blockDim.x + threadIdx.x;
    if (e >= E) return;
    int is64 = g_is64;
    int s = ld_idx(ei32, (size_t)e, is64);
    int d = ld_idx(ei32, (size_t)E + e, is64);
    g_srcs[atomicAdd(&g_wcur[d], 1)] = s;
}

// ---------------- mma.sync fused dual GEMM ----------------
// CTA: 64 rows x 256 cols ([x@W | x@res_W]), bf16x3 split, K=128.
// 8 warps: wr = wid&3 (16-row band), wc = wid>>2 (128-col half).
#define S_BHI 0
#define S_BLO 69632
#define S_STAGE 139264          // float stage[64][136]
#define SMEM_MMA (S_STAGE + 64 * 136 * 4)

__global__ void __launch_bounds__(256, 1) k_gemm_mma(
    const float* __restrict__ x, const float* __restrict__ b,
    const float* __restrict__ rb, int N)
{
    extern __shared__ char smem[];
    uint32_t* sBhi = (uint32_t*)(smem + S_BHI);
    uint32_t* sBlo = (uint32_t*)(smem + S_BLO);
    float* stage = (float*)(smem + S_STAGE);

    const int tid = threadIdx.x;
    const int wid = tid >> 5, lane = tid & 31;
    const int wr = wid & 3, wc = wid >> 2;
    const int g = lane >> 2, tg = lane & 3;

    // copy B images to smem (17408 words each = 4352 uint4)
    {
        const uint4* sh = (const uint4*)g_Bw_hi;
        const uint4* sl = (const uint4*)g_Bw_lo;
        uint4* dh = (uint4*)sBhi;
        uint4* dl = (uint4*)sBlo;
        #pragma unroll
        for (int i = 0; i < 17; i++) {
            int idx = tid + i * 256;
            dh[idx] = sh[idx];
            dl[idx] = sl[idx];
        }
    }
    __syncthreads();

    const int row0 = blockIdx.x * 64;
    const int r0 = row0 + wr * 16 + g;
    const int r1 = r0 + 8;
    const bool v0ok = r0 < N, v1ok = r1 < N;
    const float* xr0 = x + (size_t)r0 * D;
    const float* xr1 = x + (size_t)r1 * D;

    float c[16][4];
    #pragma unroll
    for (int i = 0; i < 16; i++)
        #pragma unroll
        for (int j = 0; j < 4; j++) c[i][j] = 0.f;

    #pragma unroll
    for (int ks = 0; ks < 8; ks++) {
        int k0 = ks * 16 + tg * 2;
        float2 z = make_float2(0.f, 0.f);
        float2 a00 = v0ok ? *(const float2*)(xr0 + k0)     : z;  // (r0, k0..k0+1)
        float2 a10 = v1ok ? *(const float2*)(xr1 + k0)     : z;  // (r1, ...)
        float2 a01 = v0ok ? *(const float2*)(xr0 + k0 + 8) : z;  // (r0, k0+8..+9)
        float2 a11 = v1ok ? *(const float2*)(xr1 + k0 + 8) : z;
        uint32_t ahi[4], alo[4];
        ahi[0] = pack2(a00.x, a00.y);
        ahi[1] = pack2(a10.x, a10.y);
        ahi[2] = pack2(a01.x, a01.y);
        ahi[3] = pack2(a11.x, a11.y);
        alo[0] = pack2(a00.x - bf16_hi(a00.x), a00.y - bf16_hi(a00.y));
        alo[1] = pack2(a10.x - bf16_hi(a10.x), a10.y - bf16_hi(a10.y));
        alo[2] = pack2(a01.x - bf16_hi(a01.x), a01.y - bf16_hi(a01.y));
        alo[3] = pack2(a11.x - bf16_hi(a11.x), a11.y - bf16_hi(a11.y));

        #pragma unroll
        for (int nt = 0; nt < 16; nt++) {
            int nrow = wc * 128 + nt * 8 + g;
            int w0 = nrow * BKW + ks * 8 + tg;
            uint32_t b0h = sBhi[w0], b1h = sBhi[w0 + 4];
            uint32_t b0l = sBlo[w0], b1l = sBlo[w0 + 4];
            mma_bf16(c[nt], ahi, b0h, b1h);
            mma_bf16(c[nt], ahi, b0l, b1l);
            mma_bf16(c[nt], alo, b0h, b1h);
        }
    }

    // ---- epilogue ----
    if (wc == 1) {   // residual half: stage relu(val + rb)
        #pragma unroll
        for (int nt = 0; nt < 16; nt++) {
            int col = nt * 8 + tg * 2;
            int sr0 = (wr * 16 + g) * 136 + col;
            int sr1 = (wr * 16 + g + 8) * 136 + col;
            stage[sr0]     = fmaxf(c[nt][0] + rb[col],     0.f);
            stage[sr0 + 1] = fmaxf(c[nt][1] + rb[col + 1], 0.f);
            stage[sr1]     = fmaxf(c[nt][2] + rb[col],     0.f);
            stage[sr1 + 1] = fmaxf(c[nt][3] + rb[col + 1], 0.f);
        }
    }
    __syncthreads();
    if (wc == 0) {   // main half: combine and store u + agg
        float di0 = v0ok ? g_dinv[r0] : 0.f;
        float di1 = v1ok ? g_dinv[r1] : 0.f;
        #pragma unroll
        for (int nt = 0; nt < 16; nt++) {
            int col = nt * 8 + tg * 2;
            float2 bb = *(const float2*)(b + col);
            int sr0 = (wr * 16 + g) * 136 + col;
            int sr1 = (wr * 16 + g + 8) * 136 + col;
            if (v0ok) {
                float2 u, ag;
                u.x = c[nt][0] * di0; u.y = c[nt][1] * di0;
                ag.x = u.x * di0 + bb.x + stage[sr0];
                ag.y = u.y * di0 + bb.y + stage[sr0 + 1];
                *(float2*)(g_h   + (size_t)r0 * D + col) = u;
                *(float2*)(g_agg + (size_t)r0 * D + col) = ag;
            }
            if (v1ok) {
                float2 u, ag;
                u.x = c[nt][2] * di1; u.y = c[nt][3] * di1;
                ag.x = u.x * di1 + bb.x + stage[sr1];
                ag.y = u.y * di1 + bb.y + stage[sr1 + 1];
                *(float2*)(g_h   + (size_t)r1 * D + col) = u;
                *(float2*)(g_agg + (size_t)r1 * D + col) = ag;
            }
        }
    }
}

// ---------------- CSR aggregate ----------------
__global__ void k_agg(int N) {
    int gt = blockIdx.x * blockDim.x + threadIdx.x;
    int d = gt >> 5;
    int lane = threadIdx.x & 31;
    if (d >= N) return;
    int beg = g_roff[d], end = g_roff[d + 1];
    if (beg == end) return;
    float4 acc = make_float4(0.f, 0.f, 0.f, 0.f);
    for (int j = beg; j < end; j++) {
        int s = g_srcs[j];
        float4 u = *(const float4*)(g_h + (size_t)s * D + lane * 4);
        acc.x += u.x; acc.y += u.y; acc.z += u.z; acc.w += u.w;
    }
    float di = g_dinv[d];
    float4* ap = (float4*)(g_agg + (size_t)d * D + lane * 4);
    float4 v = *ap;
    v.x += acc.x * di; v.y += acc.y * di;
    v.z += acc.z * di; v.w += acc.w * di;
    *ap = v;
}

// ---------------- BN ----------------
__global__ void k_bnsum(int N) {
    int col = threadIdx.x;
    float s = 0.f, sq = 0.f;
    for (int r = blockIdx.x; r < N; r += gridDim.x) {
        float v = g_agg[(size_t)r * D + col];
        s += v; sq += v * v;
    }
    atomicAdd(&g_sum[col], s);
    atomicAdd(&g_sumsq[col], sq);
}

__global__ void k_bnfin(const float* __restrict__ gamma,
                        const float* __restrict__ beta, int N) {
    int c = threadIdx.x;
    float inv_n = 1.0f / (float)N;
    float mean = g_sum[c] * inv_n;
    float var = fmaxf(g_sumsq[c] * inv_n - mean * mean, 0.0f);
    float sc = rsqrtf(var + 1e-5f) * gamma[c];
    g_scale[c] = sc;
    g_shift[c] = beta[c] - mean * sc;
}

__global__ void k_norm(float* __restrict__ out, int N) {
    int idx = blockIdx.x * blockDim.x + threadIdx.x;
    int total = N * (D / 4);
    if (idx >= total) return;
    int colb = (idx & 31) * 4;
    float4 v  = ((const float4*)g_agg)[idx];
    float4 sc = *(const float4*)(g_scale + colb);
    float4 sh = *(const float4*)(g_shift + colb);
    float4 o;
    o.x = v.x * sc.x + sh.x;
    o.y = v.y * sc.y + sh.y;
    o.z = v.z * sc.z + sh.z;
    o.w = v.w * sc.w + sh.w;
    ((float4*)out)[idx] = o;
}

extern "C" void kernel_launch(void* const* d_in, const int* in_sizes, int n_in,
                              void* d_out, int out_size) {
    const float* x     = (const float*)d_in[0];
    const int*   ei32  = (const int*)d_in[1];
    const float* W     = (const float*)d_in[2];
    const float* b     = (const float*)d_in[3];
    const float* rW    = (const float*)d_in[4];
    const float* rb    = (const float*)d_in[5];
    const float* gamma = (const float*)d_in[6];
    const float* beta  = (const float*)d_in[7];
    float* out = (float*)d_out;

    int N = in_sizes[0] / D;
    int E = in_sizes[1] / 2;
    int nblk = (N + SCAN_B - 1) / SCAN_B;
    int nct = (N + 63) / 64;

    cudaFuncSetAttribute(k_gemm_mma, cudaFuncAttributeMaxDynamicSharedMemorySize, SMEM_MMA);

    k_init<<<(N + 255) / 256, 256>>>(N);
    k_detect<<<4, 256>>>(ei32, E);
    k_prep<<<64, 256>>>(W, rW);
    k_hist<<<(E + 255) / 256, 256>>>(ei32, E);
    k_scan1<<<nblk, SCAN_B>>>(N);
    k_scan2<<<1, 1024>>>(nblk, N);
    k_scan3<<<nblk, SCAN_B>>>(N);
    k_fill<<<(E + 255) / 256, 256>>>(ei32, E);
    k_gemm_mma<<<nct, 256, SMEM_MMA>>>(x, b, rb, N);
    k_agg<<<(N * 32 + 255) / 256, 256>>>(N);
    k_bnsum<<<512, 128>>>(N);
    k_bnfin<<<1, 128>>>(gamma, beta, N);
    k_norm<<<(N * (D / 4) + 255) / 256, 256>>>(out, N);
}

// round 10
// speedup vs baseline: 3.1051x; 1.3473x over previous
#include <cuda_runtime.h>
#include <cuda_bf16.h>
#include <cstdint>

#define D 128
#define MAXN 100000
#define MAXE 1000000
#define SCAN_B 256
#define MAXBLK ((MAXN + SCAN_B - 1) / SCAN_B)
#define BKW 68                 // B row stride in 32-bit words (64 data + 4 pad)

// ---------------- device scratch ----------------
__device__ __align__(16) float g_h[(size_t)MAXN * D];     // u = (x@W)*dinv
__device__ __align__(16) float g_agg[(size_t)MAXN * D];   // selfloop + b + res (+ scatter)
__device__ __align__(16) float g_dinv[MAXN];
__device__ __align__(16) float g_sum[D];
__device__ __align__(16) float g_sumsq[D];
__device__ int g_cnt[MAXN];
__device__ int g_roff[MAXN + 1];
__device__ int g_wcur[MAXN];
__device__ int g_srcs[MAXE];
__device__ int g_bsum[MAXBLK];
__device__ int g_is64;
// B operand images: [n=256][kword=68] bf16x2 words; n<128 -> W col n, else res_W col n-128
__device__ __align__(16) uint32_t g_Bw_hi[256 * BKW];
__device__ __align__(16) uint32_t g_Bw_lo[256 * BKW];

__device__ __forceinline__ int ld_idx(const int* __restrict__ ei32, size_t pos, int is64) {
    return is64 ? ei32[pos << 1] : ei32[pos];
}
__device__ __forceinline__ uint32_t pack2(float a, float b) {
    __nv_bfloat162 t = __floats2bfloat162_rn(a, b);
    return *reinterpret_cast<uint32_t*>(&t);
}
__device__ __forceinline__ float bf16_hi(float v) {
    return __bfloat162float(__float2bfloat16(v));
}
__device__ __forceinline__ void mma_bf16(float* c, const uint32_t* a, uint32_t b0, uint32_t b1) {
    asm volatile(
        "mma.sync.aligned.m16n8k16.row.col.f32.bf16.bf16.f32 "
        "{%0,%1,%2,%3}, {%4,%5,%6,%7}, {%8,%9}, {%0,%1,%2,%3};"
        : "+f"(c[0]), "+f"(c[1]), "+f"(c[2]), "+f"(c[3])
        : "r"(a[0]), "r"(a[1]), "r"(a[2]), "r"(a[3]), "r"(b0), "r"(b1));
}

// ---------------- K0: init ----------------
__global__ void k_init(int N) {
    int i = blockIdx.x * blockDim.x + threadIdx.x;
    if (i < N) g_cnt[i] = 0;
    if (i < D) { g_sum[i] = 0.0f; g_sumsq[i] = 0.0f; }
    if (i == 0) g_is64 = 1;
}

__global__ void k_detect(const int* __restrict__ ei32, int E) {
    int i = blockIdx.x * blockDim.x + threadIdx.x;
    if (i < E && i < 1024) {
        if (ei32[2 * i + 1] != 0) g_is64 = 0;
    }
}

// ---------------- K_prep: build hi/lo bf16x2 B images ----------------
__global__ void k_prep(const float* __restrict__ W, const float* __restrict__ rW) {
    int t = blockIdx.x * blockDim.x + threadIdx.x;   // 16384 threads
    if (t >= 256 * 64) return;
    int n = t >> 6, kw = t & 63;
    const float* src = (n < 128) ? W : rW;
    int col = (n < 128) ? n : n - 128;
    float v0 = src[(size_t)(2 * kw) * D + col];
    float v1 = src[(size_t)(2 * kw + 1) * D + col];
    float h0 = bf16_hi(v0), h1 = bf16_hi(v1);
    g_Bw_hi[n * BKW + kw] = pack2(v0, v1);           // rn-rounded hi parts
    g_Bw_lo[n * BKW + kw] = pack2(v0 - h0, v1 - h1);
    if (kw < 4) { g_Bw_hi[n * BKW + 64 + kw] = 0; g_Bw_lo[n * BKW + 64 + kw] = 0; }
}

// ---------------- CSR build ----------------
__global__ void k_hist(const int* __restrict__ ei32, int E) {
    int e = blockIdx.x * blockDim.x + threadIdx.x;
    if (e >= E) return;
    int is64 = g_is64;
    atomicAdd(&g_cnt[ld_idx(ei32, (size_t)E + e, is64)], 1);
}

__global__ void __launch_bounds__(SCAN_B) k_scan1(int N) {
    __shared__ int red[SCAN_B / 32];
    int i = blockIdx.x * SCAN_B + threadIdx.x;
    int v = (i < N) ? g_cnt[i] : 0;
    #pragma unroll
    for (int o = 16; o > 0; o >>= 1) v += __shfl_down_sync(0xffffffff, v, o);
    int warp = threadIdx.x >> 5, lane = threadIdx.x & 31;
    if (lane == 0) red[warp] = v;
    __syncthreads();
    if (warp == 0) {
        int s = (lane < SCAN_B / 32) ? red[lane] : 0;
        #pragma unroll
        for (int o = 4; o > 0; o >>= 1) s += __shfl_down_sync(0xffffffff, s, o);
        if (lane == 0) g_bsum[blockIdx.x] = s;
    }
}

__global__ void __launch_bounds__(1024) k_scan2(int nblk, int N) {
    __shared__ int sh[1024];
    int t = threadIdx.x;
    int v = (t < nblk) ? g_bsum[t] : 0;
    sh[t] = v;
    __syncthreads();
    for (int off = 1; off < 1024; off <<= 1) {
        int u = (t >= off) ? sh[t - off] : 0;
        __syncthreads();
        sh[t] += u;
        __syncthreads();
    }
    if (t < nblk) g_bsum[t] = sh[t] - v;
    if (t == 0) g_roff[N] = sh[1023];
}

__global__ void __launch_bounds__(SCAN_B) k_scan3(int N) {
    __shared__ int wsum[SCAN_B / 32];
    int i = blockIdx.x * SCAN_B + threadIdx.x;
    int c = (i < N) ? g_cnt[i] : 0;
    int lane = threadIdx.x & 31, warp = threadIdx.x >> 5;
    int s = c;
    #pragma unroll
    for (int o = 1; o < 32; o <<= 1) {
        int u = __shfl_up_sync(0xffffffff, s, o);
        if (lane >= o) s += u;
    }
    if (lane == 31) wsum[warp] = s;
    __syncthreads();
    if (warp == 0) {
        int w = (lane < SCAN_B / 32) ? wsum[lane] : 0;
        #pragma unroll
        for (int o = 1; o < SCAN_B / 32; o <<= 1) {
            int u = __shfl_up_sync(0xffffffff, w, o);
            if (lane >= o) w += u;
        }
        if (lane < SCAN_B / 32) wsum[lane] = w;
    }
    __syncthreads();
    int excl = s - c + (warp > 0 ? wsum[warp - 1] : 0) + g_bsum[blockIdx.x];
    if (i < N) {
        g_roff[i] = excl;
        g_wcur[i] = excl;
        g_dinv[i] = rsqrtf((float)c + 1.0f);
    }
}

__global__ void k_fill(const int* __restrict__ ei32, int E) {
    int e = blockIdx.x * blockDim.x + threadIdx.x;
    if (e >= E) return;
    int is64 = g_is64;
    int s = ld_idx(ei32, (size_t)e, is64);
    int d = ld_idx(ei32, (size_t)E + e, is64);
    g_srcs[atomicAdd(&g_wcur[d], 1)] = s;
}

// ---------------- persistent mma.sync fused dual GEMM ----------------
// Tile: 64 rows x 256 cols ([x@W | x@res_W]), bf16x3 split, K=128.
// 8 warps: wr = wid&3 (16-row band), wc = wid>>2 (128-col half).
// B images loaded to SMEM once per CTA; CTA loops over tiles.
#define S_BHI 0
#define S_BLO 69632
#define S_STAGE 139264          // float stage[64][136]
#define SMEM_MMA (S_STAGE + 64 * 136 * 4)

__global__ void __launch_bounds__(256, 1) k_gemm_mma(
    const float* __restrict__ x, const float* __restrict__ b,
    const float* __restrict__ rb, int N, int ntiles)
{
    extern __shared__ char smem[];
    uint32_t* sBhi = (uint32_t*)(smem + S_BHI);
    uint32_t* sBlo = (uint32_t*)(smem + S_BLO);
    float* stage = (float*)(smem + S_STAGE);

    const int tid = threadIdx.x;
    const int wid = tid >> 5, lane = tid & 31;
    const int wr = wid & 3, wc = wid >> 2;
    const int g = lane >> 2, tg = lane & 3;

    // copy B images to smem once (17408 words each = 4352 uint4)
    {
        const uint4* sh = (const uint4*)g_Bw_hi;
        const uint4* sl = (const uint4*)g_Bw_lo;
        uint4* dh = (uint4*)sBhi;
        uint4* dl = (uint4*)sBlo;
        #pragma unroll
        for (int i = 0; i < 17; i++) {
            int idx = tid + i * 256;
            dh[idx] = sh[idx];
            dl[idx] = sl[idx];
        }
    }
    __syncthreads();

    for (int tile = blockIdx.x; tile < ntiles; tile += gridDim.x) {
        __syncthreads();    // protect stage from previous iteration's readers

        const int row0 = tile * 64;
        const int r0 = row0 + wr * 16 + g;
        const int r1 = r0 + 8;
        const bool v0ok = r0 < N, v1ok = r1 < N;
        const float* xr0 = x + (size_t)r0 * D;
        const float* xr1 = x + (size_t)r1 * D;

        float c[16][4];
        #pragma unroll
        for (int i = 0; i < 16; i++)
            #pragma unroll
            for (int j = 0; j < 4; j++) c[i][j] = 0.f;

        #pragma unroll
        for (int ks = 0; ks < 8; ks++) {
            int k0 = ks * 16 + tg * 2;
            float2 z = make_float2(0.f, 0.f);
            float2 a00 = v0ok ? *(const float2*)(xr0 + k0)     : z;
            float2 a10 = v1ok ? *(const float2*)(xr1 + k0)     : z;
            float2 a01 = v0ok ? *(const float2*)(xr0 + k0 + 8) : z;
            float2 a11 = v1ok ? *(const float2*)(xr1 + k0 + 8) : z;
            uint32_t ahi[4], alo[4];
            ahi[0] = pack2(a00.x, a00.y);
            ahi[1] = pack2(a10.x, a10.y);
            ahi[2] = pack2(a01.x, a01.y);
            ahi[3] = pack2(a11.x, a11.y);
            alo[0] = pack2(a00.x - bf16_hi(a00.x), a00.y - bf16_hi(a00.y));
            alo[1] = pack2(a10.x - bf16_hi(a10.x), a10.y - bf16_hi(a10.y));
            alo[2] = pack2(a01.x - bf16_hi(a01.x), a01.y - bf16_hi(a01.y));
            alo[3] = pack2(a11.x - bf16_hi(a11.x), a11.y - bf16_hi(a11.y));

            #pragma unroll
            for (int nt = 0; nt < 16; nt++) {
                int nrow = wc * 128 + nt * 8 + g;
                int w0 = nrow * BKW + ks * 8 + tg;
                uint32_t b0h = sBhi[w0], b1h = sBhi[w0 + 4];
                uint32_t b0l = sBlo[w0], b1l = sBlo[w0 + 4];
                mma_bf16(c[nt], ahi, b0h, b1h);
                mma_bf16(c[nt], ahi, b0l, b1l);
                mma_bf16(c[nt], alo, b0h, b1h);
            }
        }

        if (wc == 1) {   // residual half: stage relu(val + rb)
            #pragma unroll
            for (int nt = 0; nt < 16; nt++) {
                int col = nt * 8 + tg * 2;
                int sr0 = (wr * 16 + g) * 136 + col;
                int sr1 = (wr * 16 + g + 8) * 136 + col;
                stage[sr0]     = fmaxf(c[nt][0] + rb[col],     0.f);
                stage[sr0 + 1] = fmaxf(c[nt][1] + rb[col + 1], 0.f);
                stage[sr1]     = fmaxf(c[nt][2] + rb[col],     0.f);
                stage[sr1 + 1] = fmaxf(c[nt][3] + rb[col + 1], 0.f);
            }
        }
        __syncthreads();
        if (wc == 0) {   // main half: combine and store u + agg
            float di0 = v0ok ? g_dinv[r0] : 0.f;
            float di1 = v1ok ? g_dinv[r1] : 0.f;
            #pragma unroll
            for (int nt = 0; nt < 16; nt++) {
                int col = nt * 8 + tg * 2;
                float2 bb = *(const float2*)(b + col);
                int sr0 = (wr * 16 + g) * 136 + col;
                int sr1 = (wr * 16 + g + 8) * 136 + col;
                if (v0ok) {
                    float2 u, ag;
                    u.x = c[nt][0] * di0; u.y = c[nt][1] * di0;
                    ag.x = u.x * di0 + bb.x + stage[sr0];
                    ag.y = u.y * di0 + bb.y + stage[sr0 + 1];
                    *(float2*)(g_h   + (size_t)r0 * D + col) = u;
                    *(float2*)(g_agg + (size_t)r0 * D + col) = ag;
                }
                if (v1ok) {
                    float2 u, ag;
                    u.x = c[nt][2] * di1; u.y = c[nt][3] * di1;
                    ag.x = u.x * di1 + bb.x + stage[sr1];
                    ag.y = u.y * di1 + bb.y + stage[sr1 + 1];
                    *(float2*)(g_h   + (size_t)r1 * D + col) = u;
                    *(float2*)(g_agg + (size_t)r1 * D + col) = ag;
                }
            }
        }
    }
}

// ---------------- CSR aggregate + fused BN sums ----------------
// Warp per node (grid-stride). Per-lane BN partials in registers, block
// reduce in smem, one atomic per column per block.
__global__ void __launch_bounds__(256) k_agg(int N, int nwarps) {
    __shared__ float ss[8][128];
    __shared__ float sq[8][128];
    int wid = threadIdx.x >> 5, lane = threadIdx.x & 31;
    int gw = blockIdx.x * 8 + wid;
    float4 bs = make_float4(0.f, 0.f, 0.f, 0.f);
    float4 bq = make_float4(0.f, 0.f, 0.f, 0.f);

    for (int d = gw; d < N; d += nwarps) {
        int beg = g_roff[d], end = g_roff[d + 1];
        float4 acc = make_float4(0.f, 0.f, 0.f, 0.f);
        for (int j = beg; j < end; j++) {
            int s = g_srcs[j];
            float4 u = *(const float4*)(g_h + (size_t)s * D + lane * 4);
            acc.x += u.x; acc.y += u.y; acc.z += u.z; acc.w += u.w;
        }
        float di = g_dinv[d];
        float4* ap = (float4*)(g_agg + (size_t)d * D + lane * 4);
        float4 v = *ap;
        v.x += acc.x * di; v.y += acc.y * di;
        v.z += acc.z * di; v.w += acc.w * di;
        if (beg != end) *ap = v;
        bs.x += v.x; bs.y += v.y; bs.z += v.z; bs.w += v.w;
        bq.x += v.x * v.x; bq.y += v.y * v.y;
        bq.z += v.z * v.z; bq.w += v.w * v.w;
    }
    *(float4*)&ss[wid][lane * 4] = bs;
    *(float4*)&sq[wid][lane * 4] = bq;
    __syncthreads();
    int col = threadIdx.x & 127;
    if (threadIdx.x < 128) {
        float s = 0.f;
        #pragma unroll
        for (int w = 0; w < 8; w++) s += ss[w][col];
        atomicAdd(&g_sum[col], s);
    } else {
        float s = 0.f;
        #pragma unroll
        for (int w = 0; w < 8; w++) s += sq[w][col];
        atomicAdd(&g_sumsq[col], s);
    }
}

// ---------------- normalize (bnfin fused per-block) ----------------
__global__ void k_norm(const float* __restrict__ gamma, const float* __restrict__ beta,
                       float* __restrict__ out, int N) {
    __shared__ float ssc[128], ssh[128];
    int t = threadIdx.x;
    if (t < 128) {
        float inv_n = 1.0f / (float)N;
        float mean = g_sum[t] * inv_n;
        float var = fmaxf(g_sumsq[t] * inv_n - mean * mean, 0.0f);
        float sc = rsqrtf(var + 1e-5f) * gamma[t];
        ssc[t] = sc;
        ssh[t] = beta[t] - mean * sc;
    }
    __syncthreads();
    int idx = blockIdx.x * blockDim.x + t;
    int total = N * (D / 4);
    if (idx >= total) return;
    int colb = (idx & 31) * 4;
    float4 v = ((const float4*)g_agg)[idx];
    float4 o;
    o.x = v.x * ssc[colb]     + ssh[colb];
    o.y = v.y * ssc[colb + 1] + ssh[colb + 1];
    o.z = v.z * ssc[colb + 2] + ssh[colb + 2];
    o.w = v.w * ssc[colb + 3] + ssh[colb + 3];
    ((float4*)out)[idx] = o;
}

extern "C" void kernel_launch(void* const* d_in, const int* in_sizes, int n_in,
                              void* d_out, int out_size) {
    const float* x     = (const float*)d_in[0];
    const int*   ei32  = (const int*)d_in[1];
    const float* W     = (const float*)d_in[2];
    const float* b     = (const float*)d_in[3];
    const float* rW    = (const float*)d_in[4];
    const float* rb    = (const float*)d_in[5];
    const float* gamma = (const float*)d_in[6];
    const float* beta  = (const float*)d_in[7];
    float* out = (float*)d_out;

    int N = in_sizes[0] / D;
    int E = in_sizes[1] / 2;
    int nblk = (N + SCAN_B - 1) / SCAN_B;
    int ntiles = (N + 63) / 64;
    int gemm_grid = ntiles < 148 ? ntiles : 148;
    int agg_blocks = 1184;

    cudaFuncSetAttribute(k_gemm_mma, cudaFuncAttributeMaxDynamicSharedMemorySize, SMEM_MMA);

    k_init<<<(N + 255) / 256, 256>>>(N);
    k_detect<<<4, 256>>>(ei32, E);
    k_prep<<<64, 256>>>(W, rW);
    k_hist<<<(E + 255) / 256, 256>>>(ei32, E);
    k_scan1<<<nblk, SCAN_B>>>(N);
    k_scan2<<<1, 1024>>>(nblk, N);
    k_scan3<<<nblk, SCAN_B>>>(N);
    k_fill<<<(E + 255) / 256, 256>>>(ei32, E);
    k_gemm_mma<<<gemm_grid, 256, SMEM_MMA>>>(x, b, rb, N, ntiles);
    k_agg<<<agg_blocks, 256>>>(N, agg_blocks * 8);
    k_norm<<<(N * (D / 4) + 255) / 256, 256>>>(gamma, beta, out, N);
}

// round 11
// speedup vs baseline: 3.2941x; 1.0609x over previous
#include <cuda_runtime.h>
#include <cuda_bf16.h>
#include <cstdint>

#define D 128
#define MAXN 100000
#define MAXE 1000000
#define SCAN_B 256
#define MAXBLK ((MAXN + SCAN_B - 1) / SCAN_B)
#define BKW 68                 // B row stride in 32-bit words (64 data + 4 pad)

// ---------------- device scratch ----------------
__device__ __align__(16) float g_h[(size_t)MAXN * D];     // u = (x@W)*dinv
__device__ __align__(16) float g_agg[(size_t)MAXN * D];   // selfloop + b + res (+ scatter)
__device__ __align__(16) float g_dinv[MAXN];
__device__ __align__(16) float g_sum[D];
__device__ __align__(16) float g_sumsq[D];
__device__ int g_cnt[MAXN];
__device__ int g_roff[MAXN + 1];
__device__ int g_wcur[MAXN];
__device__ int g_srcs[MAXE];
__device__ int g_bsum[MAXBLK];
__device__ int g_is64;
// B operand images: [n=256][kword=68] bf16x2 words; n<128 -> W col n, else res_W col n-128
__device__ __align__(16) uint32_t g_Bw_hi[256 * BKW];
__device__ __align__(16) uint32_t g_Bw_lo[256 * BKW];

__device__ __forceinline__ int ld_idx(const int* __restrict__ ei32, size_t pos, int is64) {
    return is64 ? ei32[pos << 1] : ei32[pos];
}
__device__ __forceinline__ uint32_t pack2(float a, float b) {
    __nv_bfloat162 t = __floats2bfloat162_rn(a, b);
    return *reinterpret_cast<uint32_t*>(&t);
}
__device__ __forceinline__ float bf16_hi(float v) {
    return __bfloat162float(__float2bfloat16(v));
}
__device__ __forceinline__ void mma_bf16(float* c, const uint32_t* a, uint32_t b0, uint32_t b1) {
    asm volatile(
        "mma.sync.aligned.m16n8k16.row.col.f32.bf16.bf16.f32 "
        "{%0,%1,%2,%3}, {%4,%5,%6,%7}, {%8,%9}, {%0,%1,%2,%3};"
        : "+f"(c[0]), "+f"(c[1]), "+f"(c[2]), "+f"(c[3])
        : "r"(a[0]), "r"(a[1]), "r"(a[2]), "r"(a[3]), "r"(b0), "r"(b1));
}

// ---------------- K_setup: init + dtype-detect + B-image prep, fused ----------------
__global__ void k_setup(const int* __restrict__ ei32, int E,
                        const float* __restrict__ W, const float* __restrict__ rW, int N) {
    int i = blockIdx.x * blockDim.x + threadIdx.x;
    if (i < N) g_cnt[i] = 0;
    if (i < D) { g_sum[i] = 0.0f; g_sumsq[i] = 0.0f; }
    if (i == 0) g_is64 = 1;
    __threadfence();   // g_is64=1 visible before detection writes 0 (same kernel: use 2-phase)
    // dtype detect (writes 0 only; init value handled by separate path ordering below)
    if (i < E && i < 1024) {
        if (ei32[2 * i + 1] != 0) g_is64 = 0;
    }
    // B image prep: t in [0, 16384)
    if (i < 256 * 64) {
        int n = i >> 6, kw = i & 63;
        const float* src = (n < 128) ? W : rW;
        int col = (n < 128) ? n : n - 128;
        float v0 = src[(size_t)(2 * kw) * D + col];
        float v1 = src[(size_t)(2 * kw + 1) * D + col];
        float h0 = bf16_hi(v0), h1 = bf16_hi(v1);
        g_Bw_hi[n * BKW + kw] = pack2(v0, v1);
        g_Bw_lo[n * BKW + kw] = pack2(v0 - h0, v1 - h1);
        if (kw < 4) { g_Bw_hi[n * BKW + 64 + kw] = 0; g_Bw_lo[n * BKW + 64 + kw] = 0; }
    }
}

// ---------------- CSR build ----------------
__global__ void k_hist(const int* __restrict__ ei32, int E) {
    int e = blockIdx.x * blockDim.x + threadIdx.x;
    if (e >= E) return;
    int is64 = g_is64;
    atomicAdd(&g_cnt[ld_idx(ei32, (size_t)E + e, is64)], 1);
}

__global__ void k_dinv(int N) {
    int i = blockIdx.x * blockDim.x + threadIdx.x;
    if (i < N) g_dinv[i] = rsqrtf((float)g_cnt[i] + 1.0f);
}

__global__ void __launch_bounds__(SCAN_B) k_scan1(int N) {
    __shared__ int red[SCAN_B / 32];
    int i = blockIdx.x * SCAN_B + threadIdx.x;
    int v = (i < N) ? g_cnt[i] : 0;
    #pragma unroll
    for (int o = 16; o > 0; o >>= 1) v += __shfl_down_sync(0xffffffff, v, o);
    int warp = threadIdx.x >> 5, lane = threadIdx.x & 31;
    if (lane == 0) red[warp] = v;
    __syncthreads();
    if (warp == 0) {
        int s = (lane < SCAN_B / 32) ? red[lane] : 0;
        #pragma unroll
        for (int o = 4; o > 0; o >>= 1) s += __shfl_down_sync(0xffffffff, s, o);
        if (lane == 0) g_bsum[blockIdx.x] = s;
    }
}

__global__ void __launch_bounds__(1024) k_scan2(int nblk, int N) {
    __shared__ int sh[1024];
    int t = threadIdx.x;
    int v = (t < nblk) ? g_bsum[t] : 0;
    sh[t] = v;
    __syncthreads();
    for (int off = 1; off < 1024; off <<= 1) {
        int u = (t >= off) ? sh[t - off] : 0;
        __syncthreads();
        sh[t] += u;
        __syncthreads();
    }
    if (t < nblk) g_bsum[t] = sh[t] - v;
    if (t == 0) g_roff[N] = sh[1023];
}

__global__ void __launch_bounds__(SCAN_B) k_scan3(int N) {
    __shared__ int wsum[SCAN_B / 32];
    int i = blockIdx.x * SCAN_B + threadIdx.x;
    int c = (i < N) ? g_cnt[i] : 0;
    int lane = threadIdx.x & 31, warp = threadIdx.x >> 5;
    int s = c;
    #pragma unroll
    for (int o = 1; o < 32; o <<= 1) {
        int u = __shfl_up_sync(0xffffffff, s, o);
        if (lane >= o) s += u;
    }
    if (lane == 31) wsum[warp] = s;
    __syncthreads();
    if (warp == 0) {
        int w = (lane < SCAN_B / 32) ? wsum[lane] : 0;
        #pragma unroll
        for (int o = 1; o < SCAN_B / 32; o <<= 1) {
            int u = __shfl_up_sync(0xffffffff, w, o);
            if (lane >= o) w += u;
        }
        if (lane < SCAN_B / 32) wsum[lane] = w;
    }
    __syncthreads();
    int excl = s - c + (warp > 0 ? wsum[warp - 1] : 0) + g_bsum[blockIdx.x];
    if (i < N) {
        g_roff[i] = excl;
        g_wcur[i] = excl;
    }
}

__global__ void k_fill(const int* __restrict__ ei32, int E) {
    int e = blockIdx.x * blockDim.x + threadIdx.x;
    if (e >= E) return;
    int is64 = g_is64;
    int s = ld_idx(ei32, (size_t)e, is64);
    int d = ld_idx(ei32, (size_t)E + e, is64);
    g_srcs[atomicAdd(&g_wcur[d], 1)] = s;
}

// ---------------- persistent mma.sync fused dual GEMM ----------------
#define S_BHI 0
#define S_BLO 69632
#define S_STAGE 139264          // float stage[64][136]
#define SMEM_MMA (S_STAGE + 64 * 136 * 4)

__global__ void __launch_bounds__(256, 1) k_gemm_mma(
    const float* __restrict__ x, const float* __restrict__ b,
    const float* __restrict__ rb, int N, int ntiles)
{
    extern __shared__ char smem[];
    uint32_t* sBhi = (uint32_t*)(smem + S_BHI);
    uint32_t* sBlo = (uint32_t*)(smem + S_BLO);
    float* stage = (float*)(smem + S_STAGE);

    const int tid = threadIdx.x;
    const int wid = tid >> 5, lane = tid & 31;
    const int wr = wid & 3, wc = wid >> 2;
    const int g = lane >> 2, tg = lane & 3;

    {
        const uint4* sh = (const uint4*)g_Bw_hi;
        const uint4* sl = (const uint4*)g_Bw_lo;
        uint4* dh = (uint4*)sBhi;
        uint4* dl = (uint4*)sBlo;
        #pragma unroll
        for (int i = 0; i < 17; i++) {
            int idx = tid + i * 256;
            dh[idx] = sh[idx];
            dl[idx] = sl[idx];
        }
    }
    __syncthreads();

    for (int tile = blockIdx.x; tile < ntiles; tile += gridDim.x) {
        __syncthreads();

        const int row0 = tile * 64;
        const int r0 = row0 + wr * 16 + g;
        const int r1 = r0 + 8;
        const bool v0ok = r0 < N, v1ok = r1 < N;
        const float* xr0 = x + (size_t)r0 * D;
        const float* xr1 = x + (size_t)r1 * D;

        float c[16][4];
        #pragma unroll
        for (int i = 0; i < 16; i++)
            #pragma unroll
            for (int j = 0; j < 4; j++) c[i][j] = 0.f;

        #pragma unroll
        for (int ks = 0; ks < 8; ks++) {
            int k0 = ks * 16 + tg * 2;
            float2 z = make_float2(0.f, 0.f);
            float2 a00 = v0ok ? *(const float2*)(xr0 + k0)     : z;
            float2 a10 = v1ok ? *(const float2*)(xr1 + k0)     : z;
            float2 a01 = v0ok ? *(const float2*)(xr0 + k0 + 8) : z;
            float2 a11 = v1ok ? *(const float2*)(xr1 + k0 + 8) : z;
            uint32_t ahi[4], alo[4];
            ahi[0] = pack2(a00.x, a00.y);
            ahi[1] = pack2(a10.x, a10.y);
            ahi[2] = pack2(a01.x, a01.y);
            ahi[3] = pack2(a11.x, a11.y);
            alo[0] = pack2(a00.x - bf16_hi(a00.x), a00.y - bf16_hi(a00.y));
            alo[1] = pack2(a10.x - bf16_hi(a10.x), a10.y - bf16_hi(a10.y));
            alo[2] = pack2(a01.x - bf16_hi(a01.x), a01.y - bf16_hi(a01.y));
            alo[3] = pack2(a11.x - bf16_hi(a11.x), a11.y - bf16_hi(a11.y));

            #pragma unroll
            for (int nt = 0; nt < 16; nt++) {
                int nrow = wc * 128 + nt * 8 + g;
                int w0 = nrow * BKW + ks * 8 + tg;
                uint32_t b0h = sBhi[w0], b1h = sBhi[w0 + 4];
                uint32_t b0l = sBlo[w0], b1l = sBlo[w0 + 4];
                mma_bf16(c[nt], ahi, b0h, b1h);
                mma_bf16(c[nt], ahi, b0l, b1l);
                mma_bf16(c[nt], alo, b0h, b1h);
            }
        }

        if (wc == 1) {
            #pragma unroll
            for (int nt = 0; nt < 16; nt++) {
                int col = nt * 8 + tg * 2;
                int sr0 = (wr * 16 + g) * 136 + col;
                int sr1 = (wr * 16 + g + 8) * 136 + col;
                stage[sr0]     = fmaxf(c[nt][0] + rb[col],     0.f);
                stage[sr0 + 1] = fmaxf(c[nt][1] + rb[col + 1], 0.f);
                stage[sr1]     = fmaxf(c[nt][2] + rb[col],     0.f);
                stage[sr1 + 1] = fmaxf(c[nt][3] + rb[col + 1], 0.f);
            }
        }
        __syncthreads();
        if (wc == 0) {
            float di0 = v0ok ? g_dinv[r0] : 0.f;
            float di1 = v1ok ? g_dinv[r1] : 0.f;
            #pragma unroll
            for (int nt = 0; nt < 16; nt++) {
                int col = nt * 8 + tg * 2;
                float2 bb = *(const float2*)(b + col);
                int sr0 = (wr * 16 + g) * 136 + col;
                int sr1 = (wr * 16 + g + 8) * 136 + col;
                if (v0ok) {
                    float2 u, ag;
                    u.x = c[nt][0] * di0; u.y = c[nt][1] * di0;
                    ag.x = u.x * di0 + bb.x + stage[sr0];
                    ag.y = u.y * di0 + bb.y + stage[sr0 + 1];
                    *(float2*)(g_h   + (size_t)r0 * D + col) = u;
                    *(float2*)(g_agg + (size_t)r0 * D + col) = ag;
                }
                if (v1ok) {
                    float2 u, ag;
                    u.x = c[nt][2] * di1; u.y = c[nt][3] * di1;
                    ag.x = u.x * di1 + bb.x + stage[sr1];
                    ag.y = u.y * di1 + bb.y + stage[sr1 + 1];
                    *(float2*)(g_h   + (size_t)r1 * D + col) = u;
                    *(float2*)(g_agg + (size_t)r1 * D + col) = ag;
                }
            }
        }
    }
}

// ---------------- CSR aggregate + fused BN sums ----------------
__global__ void __launch_bounds__(256) k_agg(int N, int nwarps) {
    __shared__ float ss[8][128];
    __shared__ float sq[8][128];
    int wid = threadIdx.x >> 5, lane = threadIdx.x & 31;
    int gw = blockIdx.x * 8 + wid;
    float4 bs = make_float4(0.f, 0.f, 0.f, 0.f);
    float4 bq = make_float4(0.f, 0.f, 0.f, 0.f);

    for (int d = gw; d < N; d += nwarps) {
        int beg = g_roff[d], end = g_roff[d + 1];
        float4 acc = make_float4(0.f, 0.f, 0.f, 0.f);
        for (int j = beg; j < end; j++) {
            int s = g_srcs[j];
            float4 u = *(const float4*)(g_h + (size_t)s * D + lane * 4);
            acc.x += u.x; acc.y += u.y; acc.z += u.z; acc.w += u.w;
        }
        float di = g_dinv[d];
        float4* ap = (float4*)(g_agg + (size_t)d * D + lane * 4);
        float4 v = *ap;
        v.x += acc.x * di; v.y += acc.y * di;
        v.z += acc.z * di; v.w += acc.w * di;
        if (beg != end) *ap = v;
        bs.x += v.x; bs.y += v.y; bs.z += v.z; bs.w += v.w;
        bq.x += v.x * v.x; bq.y += v.y * v.y;
        bq.z += v.z * v.z; bq.w += v.w * v.w;
    }
    *(float4*)&ss[wid][lane * 4] = bs;
    *(float4*)&sq[wid][lane * 4] = bq;
    __syncthreads();
    int col = threadIdx.x & 127;
    if (threadIdx.x < 128) {
        float s = 0.f;
        #pragma unroll
        for (int w = 0; w < 8; w++) s += ss[w][col];
        atomicAdd(&g_sum[col], s);
    } else {
        float s = 0.f;
        #pragma unroll
        for (int w = 0; w < 8; w++) s += sq[w][col];
        atomicAdd(&g_sumsq[col], s);
    }
}

// ---------------- normalize (bnfin fused per-block) ----------------
__global__ void k_norm(const float* __restrict__ gamma, const float* __restrict__ beta,
                       float* __restrict__ out, int N) {
    __shared__ float ssc[128], ssh[128];
    int t = threadIdx.x;
    if (t < 128) {
        float inv_n = 1.0f / (float)N;
        float mean = g_sum[t] * inv_n;
        float var = fmaxf(g_sumsq[t] * inv_n - mean * mean, 0.0f);
        float sc = rsqrtf(var + 1e-5f) * gamma[t];
        ssc[t] = sc;
        ssh[t] = beta[t] - mean * sc;
    }
    __syncthreads();
    int idx = blockIdx.x * blockDim.x + t;
    int total = N * (D / 4);
    if (idx >= total) return;
    int colb = (idx & 31) * 4;
    float4 v = ((const float4*)g_agg)[idx];
    float4 o;
    o.x = v.x * ssc[colb]     + ssh[colb];
    o.y = v.y * ssc[colb + 1] + ssh[colb + 1];
    o.z = v.z * ssc[colb + 2] + ssh[colb + 2];
    o.w = v.w * ssc[colb + 3] + ssh[colb + 3];
    ((float4*)out)[idx] = o;
}

extern "C" void kernel_launch(void* const* d_in, const int* in_sizes, int n_in,
                              void* d_out, int out_size) {
    const float* x     = (const float*)d_in[0];
    const int*   ei32  = (const int*)d_in[1];
    const float* W     = (const float*)d_in[2];
    const float* b     = (const float*)d_in[3];
    const float* rW    = (const float*)d_in[4];
    const float* rb    = (const float*)d_in[5];
    const float* gamma = (const float*)d_in[6];
    const float* beta  = (const float*)d_in[7];
    float* out = (float*)d_out;

    int N = in_sizes[0] / D;
    int E = in_sizes[1] / 2;
    int nblk = (N + SCAN_B - 1) / SCAN_B;
    int ntiles = (N + 63) / 64;
    int gemm_grid = ntiles < 148 ? ntiles : 148;
    int agg_blocks = 1184;

    cudaFuncSetAttribute(k_gemm_mma, cudaFuncAttributeMaxDynamicSharedMemorySize, SMEM_MMA);

    // fork/join resources (created+destroyed per call; only kernel nodes get captured)
    cudaStream_t s2;
    cudaStreamCreateWithFlags(&s2, cudaStreamNonBlocking);
    cudaEvent_t evFork, evJoin;
    cudaEventCreateWithFlags(&evFork, cudaEventDisableTiming);
    cudaEventCreateWithFlags(&evJoin, cudaEventDisableTiming);

    // main stream: setup -> hist
    k_setup<<<(N + 255) / 256, 256>>>(ei32, E, W, rW, N);
    k_hist<<<(E + 255) / 256, 256>>>(ei32, E);

    // fork: scan+fill on s2, dinv+gemm on main
    cudaEventRecord(evFork, 0);
    cudaStreamWaitEvent(s2, evFork, 0);

    k_scan1<<<nblk, SCAN_B, 0, s2>>>(N);
    k_scan2<<<1, 1024, 0, s2>>>(nblk, N);
    k_scan3<<<nblk, SCAN_B, 0, s2>>>(N);
    k_fill<<<(E + 255) / 256, 256, 0, s2>>>(ei32, E);
    cudaEventRecord(evJoin, s2);

    k_dinv<<<(N + 255) / 256, 256>>>(N);
    k_gemm_mma<<<gemm_grid, 256, SMEM_MMA>>>(x, b, rb, N, ntiles);

    // join, then aggregate + normalize
    cudaStreamWaitEvent(0, evJoin, 0);
    k_agg<<<agg_blocks, 256>>>(N, agg_blocks * 8);
    k_norm<<<(N * (D / 4) + 255) / 256, 256>>>(gamma, beta, out, N);

    cudaEventDestroy(evFork);
    cudaEventDestroy(evJoin);
    cudaStreamDestroy(s2);
}

// round 12
// speedup vs baseline: 3.4369x; 1.0433x over previous
#include <cuda_runtime.h>
#include <cuda_bf16.h>
#include <cstdint>

#define D 128
#define MAXN 100000
#define MAXE 1000000
#define SCAN_B 256
#define MAXBLK ((MAXN + SCAN_B - 1) / SCAN_B)
#define BKW 68                 // B row stride in 32-bit words (64 data + 4 pad)

// ---------------- device scratch ----------------
__device__ __align__(16) float g_h[(size_t)MAXN * D];     // u = (x@W)*dinv
__device__ __align__(16) float g_agg[(size_t)MAXN * D];   // selfloop + b + res (+ scatter)
__device__ __align__(16) float g_sum[D];
__device__ __align__(16) float g_sumsq[D];
__device__ int g_cnt[MAXN];
__device__ int g_roff[MAXN + 1];
__device__ int g_wcur[MAXN];
__device__ int g_srcs[MAXE];
__device__ int g_bsum[MAXBLK];
__device__ int g_is64;
// B operand images: [n=256][kword=68] bf16x2 words; n<128 -> W col n, else res_W col n-128
__device__ __align__(16) uint32_t g_Bw_hi[256 * BKW];
__device__ __align__(16) uint32_t g_Bw_lo[256 * BKW];

__device__ __forceinline__ int ld_idx(const int* __restrict__ ei32, size_t pos, int is64) {
    return is64 ? ei32[pos << 1] : ei32[pos];
}
__device__ __forceinline__ uint32_t pack2(float a, float b) {
    __nv_bfloat162 t = __floats2bfloat162_rn(a, b);
    return *reinterpret_cast<uint32_t*>(&t);
}
__device__ __forceinline__ float bf16_hi(float v) {
    return __bfloat162float(__float2bfloat16(v));
}
__device__ __forceinline__ void mma_bf16(float* c, const uint32_t* a, uint32_t b0, uint32_t b1) {
    asm volatile(
        "mma.sync.aligned.m16n8k16.row.col.f32.bf16.bf16.f32 "
        "{%0,%1,%2,%3}, {%4,%5,%6,%7}, {%8,%9}, {%0,%1,%2,%3};"
        : "+f"(c[0]), "+f"(c[1]), "+f"(c[2]), "+f"(c[3])
        : "r"(a[0]), "r"(a[1]), "r"(a[2]), "r"(a[3]), "r"(b0), "r"(b1));
}

// ---------------- K_setup: init + dtype-detect + B-image prep ----------------
__global__ void k_setup(const int* __restrict__ ei32, int E,
                        const float* __restrict__ W, const float* __restrict__ rW, int N) {
    int i = blockIdx.x * blockDim.x + threadIdx.x;
    if (i < N) g_cnt[i] = 0;
    if (i < D) { g_sum[i] = 0.0f; g_sumsq[i] = 0.0f; }
    if (i == 0) g_is64 = 1;
    __threadfence();
    if (i < E && i < 1024) {
        if (ei32[2 * i + 1] != 0) g_is64 = 0;
    }
    if (i < 256 * 64) {
        int n = i >> 6, kw = i & 63;
        const float* src = (n < 128) ? W : rW;
        int col = (n < 128) ? n : n - 128;
        float v0 = src[(size_t)(2 * kw) * D + col];
        float v1 = src[(size_t)(2 * kw + 1) * D + col];
        float h0 = bf16_hi(v0), h1 = bf16_hi(v1);
        g_Bw_hi[n * BKW + kw] = pack2(v0, v1);
        g_Bw_lo[n * BKW + kw] = pack2(v0 - h0, v1 - h1);
        if (kw < 4) { g_Bw_hi[n * BKW + 64 + kw] = 0; g_Bw_lo[n * BKW + 64 + kw] = 0; }
    }
}

// ---------------- CSR build ----------------
__global__ void k_hist(const int* __restrict__ ei32, int E) {
    int e = blockIdx.x * blockDim.x + threadIdx.x;
    if (e >= E) return;
    int is64 = g_is64;
    atomicAdd(&g_cnt[ld_idx(ei32, (size_t)E + e, is64)], 1);
}

__global__ void __launch_bounds__(SCAN_B) k_scan1(int N) {
    __shared__ int red[SCAN_B / 32];
    int i = blockIdx.x * SCAN_B + threadIdx.x;
    int v = (i < N) ? g_cnt[i] : 0;
    #pragma unroll
    for (int o = 16; o > 0; o >>= 1) v += __shfl_down_sync(0xffffffff, v, o);
    int warp = threadIdx.x >> 5, lane = threadIdx.x & 31;
    if (lane == 0) red[warp] = v;
    __syncthreads();
    if (warp == 0) {
        int s = (lane < SCAN_B / 32) ? red[lane] : 0;
        #pragma unroll
        for (int o = 4; o > 0; o >>= 1) s += __shfl_down_sync(0xffffffff, s, o);
        if (lane == 0) g_bsum[blockIdx.x] = s;
    }
}

__global__ void __launch_bounds__(1024) k_scan2(int nblk, int N) {
    __shared__ int sh[1024];
    int t = threadIdx.x;
    int v = (t < nblk) ? g_bsum[t] : 0;
    sh[t] = v;
    __syncthreads();
    for (int off = 1; off < 1024; off <<= 1) {
        int u = (t >= off) ? sh[t - off] : 0;
        __syncthreads();
        sh[t] += u;
        __syncthreads();
    }
    if (t < nblk) g_bsum[t] = sh[t] - v;
    if (t == 0) g_roff[N] = sh[1023];
}

__global__ void __launch_bounds__(SCAN_B) k_scan3(int N) {
    __shared__ int wsum[SCAN_B / 32];
    int i = blockIdx.x * SCAN_B + threadIdx.x;
    int c = (i < N) ? g_cnt[i] : 0;
    int lane = threadIdx.x & 31, warp = threadIdx.x >> 5;
    int s = c;
    #pragma unroll
    for (int o = 1; o < 32; o <<= 1) {
        int u = __shfl_up_sync(0xffffffff, s, o);
        if (lane >= o) s += u;
    }
    if (lane == 31) wsum[warp] = s;
    __syncthreads();
    if (warp == 0) {
        int w = (lane < SCAN_B / 32) ? wsum[lane] : 0;
        #pragma unroll
        for (int o = 1; o < SCAN_B / 32; o <<= 1) {
            int u = __shfl_up_sync(0xffffffff, w, o);
            if (lane >= o) w += u;
        }
        if (lane < SCAN_B / 32) wsum[lane] = w;
    }
    __syncthreads();
    int excl = s - c + (warp > 0 ? wsum[warp - 1] : 0) + g_bsum[blockIdx.x];
    if (i < N) {
        g_roff[i] = excl;
        g_wcur[i] = excl;
    }
}

__global__ void k_fill(const int* __restrict__ ei32, int E) {
    int e = blockIdx.x * blockDim.x + threadIdx.x;
    if (e >= E) return;
    int is64 = g_is64;
    int s = ld_idx(ei32, (size_t)e, is64);
    int d = ld_idx(ei32, (size_t)E + e, is64);
    g_srcs[atomicAdd(&g_wcur[d], 1)] = s;
}

// ---------------- persistent mma.sync fused dual GEMM ----------------
// Tile: 128 rows x 256 cols; 8 warps: wr = wid&3 (32-row band, TWO m16 frags
// sharing each B load), wc = wid>>2 (128-col half). bf16x3 split, K=128.
#define S_BHI 0
#define S_BLO 69632
#define S_STAGE 139264          // float stage[128][136]
#define SMEM_MMA (S_STAGE + 128 * 136 * 4)

__global__ void __launch_bounds__(256, 1) k_gemm_mma(
    const float* __restrict__ x, const float* __restrict__ b,
    const float* __restrict__ rb, int N, int ntiles)
{
    extern __shared__ char smem[];
    uint32_t* sBhi = (uint32_t*)(smem + S_BHI);
    uint32_t* sBlo = (uint32_t*)(smem + S_BLO);
    float* stage = (float*)(smem + S_STAGE);

    const int tid = threadIdx.x;
    const int wid = tid >> 5, lane = tid & 31;
    const int wr = wid & 3, wc = wid >> 2;
    const int g = lane >> 2, tg = lane & 3;

    {
        const uint4* sh = (const uint4*)g_Bw_hi;
        const uint4* sl = (const uint4*)g_Bw_lo;
        uint4* dh = (uint4*)sBhi;
        uint4* dl = (uint4*)sBlo;
        #pragma unroll
        for (int i = 0; i < 17; i++) {
            int idx = tid + i * 256;
            dh[idx] = sh[idx];
            dl[idx] = sl[idx];
        }
    }
    __syncthreads();

    for (int tile = blockIdx.x; tile < ntiles; tile += gridDim.x) {
        __syncthreads();

        const int base = tile * 128 + wr * 32;
        const int rA0 = base + g,      rA1 = base + 8 + g;    // frag 0
        const int rB0 = base + 16 + g, rB1 = base + 24 + g;   // frag 1
        const bool okA0 = rA0 < N, okA1 = rA1 < N, okB0 = rB0 < N, okB1 = rB1 < N;
        const float* xA0 = x + (size_t)rA0 * D;
        const float* xA1 = x + (size_t)rA1 * D;
        const float* xB0 = x + (size_t)rB0 * D;
        const float* xB1 = x + (size_t)rB1 * D;

        float c0[16][4], c1[16][4];
        #pragma unroll
        for (int i = 0; i < 16; i++)
            #pragma unroll
            for (int j = 0; j < 4; j++) { c0[i][j] = 0.f; c1[i][j] = 0.f; }

        #pragma unroll
        for (int ks = 0; ks < 8; ks++) {
            int k0 = ks * 16 + tg * 2;
            float2 z = make_float2(0.f, 0.f);
            float2 a00 = okA0 ? *(const float2*)(xA0 + k0)     : z;
            float2 a10 = okA1 ? *(const float2*)(xA1 + k0)     : z;
            float2 a01 = okA0 ? *(const float2*)(xA0 + k0 + 8) : z;
            float2 a11 = okA1 ? *(const float2*)(xA1 + k0 + 8) : z;
            float2 b00 = okB0 ? *(const float2*)(xB0 + k0)     : z;
            float2 b10 = okB1 ? *(const float2*)(xB1 + k0)     : z;
            float2 b01 = okB0 ? *(const float2*)(xB0 + k0 + 8) : z;
            float2 b11 = okB1 ? *(const float2*)(xB1 + k0 + 8) : z;
            uint32_t ahi0[4], alo0[4], ahi1[4], alo1[4];
            ahi0[0] = pack2(a00.x, a00.y); ahi0[1] = pack2(a10.x, a10.y);
            ahi0[2] = pack2(a01.x, a01.y); ahi0[3] = pack2(a11.x, a11.y);
            alo0[0] = pack2(a00.x - bf16_hi(a00.x), a00.y - bf16_hi(a00.y));
            alo0[1] = pack2(a10.x - bf16_hi(a10.x), a10.y - bf16_hi(a10.y));
            alo0[2] = pack2(a01.x - bf16_hi(a01.x), a01.y - bf16_hi(a01.y));
            alo0[3] = pack2(a11.x - bf16_hi(a11.x), a11.y - bf16_hi(a11.y));
            ahi1[0] = pack2(b00.x, b00.y); ahi1[1] = pack2(b10.x, b10.y);
            ahi1[2] = pack2(b01.x, b01.y); ahi1[3] = pack2(b11.x, b11.y);
            alo1[0] = pack2(b00.x - bf16_hi(b00.x), b00.y - bf16_hi(b00.y));
            alo1[1] = pack2(b10.x - bf16_hi(b10.x), b10.y - bf16_hi(b10.y));
            alo1[2] = pack2(b01.x - bf16_hi(b01.x), b01.y - bf16_hi(b01.y));
            alo1[3] = pack2(b11.x - bf16_hi(b11.x), b11.y - bf16_hi(b11.y));

            #pragma unroll
            for (int nt = 0; nt < 16; nt++) {
                int nrow = wc * 128 + nt * 8 + g;
                int w0 = nrow * BKW + ks * 8 + tg;
                uint32_t b0h = sBhi[w0], b1h = sBhi[w0 + 4];
                uint32_t b0l = sBlo[w0], b1l = sBlo[w0 + 4];
                mma_bf16(c0[nt], ahi0, b0h, b1h);
                mma_bf16(c0[nt], ahi0, b0l, b1l);
                mma_bf16(c0[nt], alo0, b0h, b1h);
                mma_bf16(c1[nt], ahi1, b0h, b1h);
                mma_bf16(c1[nt], ahi1, b0l, b1l);
                mma_bf16(c1[nt], alo1, b0h, b1h);
            }
        }

        int lr = wr * 32 + g;    // local row of frag0-row0
        if (wc == 1) {   // residual half: stage relu(val + rb)
            #pragma unroll
            for (int nt = 0; nt < 16; nt++) {
                int col = nt * 8 + tg * 2;
                float rb0 = rb[col], rb1 = rb[col + 1];
                stage[(lr)      * 136 + col]     = fmaxf(c0[nt][0] + rb0, 0.f);
                stage[(lr)      * 136 + col + 1] = fmaxf(c0[nt][1] + rb1, 0.f);
                stage[(lr + 8)  * 136 + col]     = fmaxf(c0[nt][2] + rb0, 0.f);
                stage[(lr + 8)  * 136 + col + 1] = fmaxf(c0[nt][3] + rb1, 0.f);
                stage[(lr + 16) * 136 + col]     = fmaxf(c1[nt][0] + rb0, 0.f);
                stage[(lr + 16) * 136 + col + 1] = fmaxf(c1[nt][1] + rb1, 0.f);
                stage[(lr + 24) * 136 + col]     = fmaxf(c1[nt][2] + rb0, 0.f);
                stage[(lr + 24) * 136 + col + 1] = fmaxf(c1[nt][3] + rb1, 0.f);
            }
        }
        __syncthreads();
        if (wc == 0) {   // main half: combine and store u + agg
            float diA0 = okA0 ? rsqrtf((float)g_cnt[rA0] + 1.0f) : 0.f;
            float diA1 = okA1 ? rsqrtf((float)g_cnt[rA1] + 1.0f) : 0.f;
            float diB0 = okB0 ? rsqrtf((float)g_cnt[rB0] + 1.0f) : 0.f;
            float diB1 = okB1 ? rsqrtf((float)g_cnt[rB1] + 1.0f) : 0.f;
            #pragma unroll
            for (int nt = 0; nt < 16; nt++) {
                int col = nt * 8 + tg * 2;
                float2 bb = *(const float2*)(b + col);
                #pragma unroll
                for (int f = 0; f < 4; f++) {
                    int r = (f == 0) ? rA0 : (f == 1) ? rA1 : (f == 2) ? rB0 : rB1;
                    bool ok = (f == 0) ? okA0 : (f == 1) ? okA1 : (f == 2) ? okB0 : okB1;
                    if (!ok) continue;
                    float di = (f == 0) ? diA0 : (f == 1) ? diA1 : (f == 2) ? diB0 : diB1;
                    const float* cc = (f < 2) ? c0[nt] : c1[nt];
                    float v0 = (f & 1) ? cc[2] : cc[0];
                    float v1 = (f & 1) ? cc[3] : cc[1];
                    int srow = lr + ((f & 1) ? 8 : 0) + ((f >> 1) ? 16 : 0);
                    float2 u, ag;
                    u.x = v0 * di; u.y = v1 * di;
                    ag.x = u.x * di + bb.x + stage[srow * 136 + col];
                    ag.y = u.y * di + bb.y + stage[srow * 136 + col + 1];
                    *(float2*)(g_h   + (size_t)r * D + col) = u;
                    *(float2*)(g_agg + (size_t)r * D + col) = ag;
                }
            }
        }
    }
}

// ---------------- CSR aggregate + fused BN sums ----------------
__global__ void __launch_bounds__(256) k_agg(int N, int nwarps) {
    __shared__ float ss[8][128];
    __shared__ float sq[8][128];
    int wid = threadIdx.x >> 5, lane = threadIdx.x & 31;
    int gw = blockIdx.x * 8 + wid;
    float4 bs = make_float4(0.f, 0.f, 0.f, 0.f);
    float4 bq = make_float4(0.f, 0.f, 0.f, 0.f);

    for (int d = gw; d < N; d += nwarps) {
        int beg = g_roff[d], end = g_roff[d + 1];
        float4 acc = make_float4(0.f, 0.f, 0.f, 0.f);
        for (int j = beg; j < end; j++) {
            int s = g_srcs[j];
            float4 u = *(const float4*)(g_h + (size_t)s * D + lane * 4);
            acc.x += u.x; acc.y += u.y; acc.z += u.z; acc.w += u.w;
        }
        float di = rsqrtf((float)(end - beg) + 1.0f);
        float4* ap = (float4*)(g_agg + (size_t)d * D + lane * 4);
        float4 v = *ap;
        v.x += acc.x * di; v.y += acc.y * di;
        v.z += acc.z * di; v.w += acc.w * di;
        if (beg != end) *ap = v;
        bs.x += v.x; bs.y += v.y; bs.z += v.z; bs.w += v.w;
        bq.x += v.x * v.x; bq.y += v.y * v.y;
        bq.z += v.z * v.z; bq.w += v.w * v.w;
    }
    *(float4*)&ss[wid][lane * 4] = bs;
    *(float4*)&sq[wid][lane * 4] = bq;
    __syncthreads();
    int col = threadIdx.x & 127;
    if (threadIdx.x < 128) {
        float s = 0.f;
        #pragma unroll
        for (int w = 0; w < 8; w++) s += ss[w][col];
        atomicAdd(&g_sum[col], s);
    } else {
        float s = 0.f;
        #pragma unroll
        for (int w = 0; w < 8; w++) s += sq[w][col];
        atomicAdd(&g_sumsq[col], s);
    }
}

// ---------------- normalize (bnfin fused per-block) ----------------
__global__ void k_norm(const float* __restrict__ gamma, const float* __restrict__ beta,
                       float* __restrict__ out, int N) {
    __shared__ float ssc[128], ssh[128];
    int t = threadIdx.x;
    if (t < 128) {
        float inv_n = 1.0f / (float)N;
        float mean = g_sum[t] * inv_n;
        float var = fmaxf(g_sumsq[t] * inv_n - mean * mean, 0.0f);
        float sc = rsqrtf(var + 1e-5f) * gamma[t];
        ssc[t] = sc;
        ssh[t] = beta[t] - mean * sc;
    }
    __syncthreads();
    int idx = blockIdx.x * blockDim.x + t;
    int total = N * (D / 4);
    if (idx >= total) return;
    int colb = (idx & 31) * 4;
    float4 v = ((const float4*)g_agg)[idx];
    float4 o;
    o.x = v.x * ssc[colb]     + ssh[colb];
    o.y = v.y * ssc[colb + 1] + ssh[colb + 1];
    o.z = v.z * ssc[colb + 2] + ssh[colb + 2];
    o.w = v.w * ssc[colb + 3] + ssh[colb + 3];
    ((float4*)out)[idx] = o;
}

extern "C" void kernel_launch(void* const* d_in, const int* in_sizes, int n_in,
                              void* d_out, int out_size) {
    const float* x     = (const float*)d_in[0];
    const int*   ei32  = (const int*)d_in[1];
    const float* W     = (const float*)d_in[2];
    const float* b     = (const float*)d_in[3];
    const float* rW    = (const float*)d_in[4];
    const float* rb    = (const float*)d_in[5];
    const float* gamma = (const float*)d_in[6];
    const float* beta  = (const float*)d_in[7];
    float* out = (float*)d_out;

    int N = in_sizes[0] / D;
    int E = in_sizes[1] / 2;
    int nblk = (N + SCAN_B - 1) / SCAN_B;
    int ntiles = (N + 127) / 128;
    int gemm_grid = ntiles < 148 ? ntiles : 148;
    int agg_blocks = 1184;

    cudaFuncSetAttribute(k_gemm_mma, cudaFuncAttributeMaxDynamicSharedMemorySize, SMEM_MMA);

    cudaStream_t s2;
    cudaStreamCreateWithFlags(&s2, cudaStreamNonBlocking);
    cudaEvent_t evFork, evJoin;
    cudaEventCreateWithFlags(&evFork, cudaEventDisableTiming);
    cudaEventCreateWithFlags(&evJoin, cudaEventDisableTiming);

    k_setup<<<(N + 255) / 256, 256>>>(ei32, E, W, rW, N);
    k_hist<<<(E + 255) / 256, 256>>>(ei32, E);

    cudaEventRecord(evFork, 0);
    cudaStreamWaitEvent(s2, evFork, 0);

    k_scan1<<<nblk, SCAN_B, 0, s2>>>(N);
    k_scan2<<<1, 1024, 0, s2>>>(nblk, N);
    k_scan3<<<nblk, SCAN_B, 0, s2>>>(N);
    k_fill<<<(E + 255) / 256, 256, 0, s2>>>(ei32, E);
    cudaEventRecord(evJoin, s2);

    k_gemm_mma<<<gemm_grid, 256, SMEM_MMA>>>(x, b, rb, N, ntiles);

    cudaStreamWaitEvent(0, evJoin, 0);
    k_agg<<<agg_blocks, 256>>>(N, agg_blocks * 8);
    k_norm<<<(N * (D / 4) + 255) / 256, 256>>>(gamma, beta, out, N);

    cudaEventDestroy(evFork);
    cudaEventDestroy(evJoin);
    cudaStreamDestroy(s2);
}

// round 13
// speedup vs baseline: 3.5357x; 1.0288x over previous
#include <cuda_runtime.h>
#include <cuda_bf16.h>
#include <cstdint>

#define D 128
#define MAXN 100000
#define MAXE 1000000
#define SCAN_B 256
#define MAXBLK ((MAXN + SCAN_B - 1) / SCAN_B)
#define BKW 68                 // B row stride in 32-bit words (64 data + 4 pad)

// ---------------- device scratch ----------------
__device__ __align__(16) float g_h[(size_t)MAXN * D];     // raw h = x@W
__device__ __align__(16) float g_agg[(size_t)MAXN * D];   // b + relu(res), then final y
__device__ __align__(16) float g_dinv[MAXN];
__device__ __align__(16) float g_sum[D];
__device__ __align__(16) float g_sumsq[D];
__device__ int g_cnt[MAXN];
__device__ int g_roff[MAXN + 1];
__device__ int g_wcur[MAXN];
__device__ int g_srcs[MAXE];
__device__ int g_bsum[MAXBLK];
__device__ int g_is64;
// B operand images: [n=256][kword=68] bf16x2 words; n<128 -> W col n, else res_W col n-128
__device__ __align__(16) uint32_t g_Bw_hi[256 * BKW];
__device__ __align__(16) uint32_t g_Bw_lo[256 * BKW];

__device__ __forceinline__ int ld_idx(const int* __restrict__ ei32, size_t pos, int is64) {
    return is64 ? ei32[pos << 1] : ei32[pos];
}
__device__ __forceinline__ uint32_t pack2(float a, float b) {
    __nv_bfloat162 t = __floats2bfloat162_rn(a, b);
    return *reinterpret_cast<uint32_t*>(&t);
}
__device__ __forceinline__ float bf16_hi(float v) {
    return __bfloat162float(__float2bfloat16(v));
}
__device__ __forceinline__ void mma_bf16(float* c, const uint32_t* a, uint32_t b0, uint32_t b1) {
    asm volatile(
        "mma.sync.aligned.m16n8k16.row.col.f32.bf16.bf16.f32 "
        "{%0,%1,%2,%3}, {%4,%5,%6,%7}, {%8,%9}, {%0,%1,%2,%3};"
        : "+f"(c[0]), "+f"(c[1]), "+f"(c[2]), "+f"(c[3])
        : "r"(a[0]), "r"(a[1]), "r"(a[2]), "r"(a[3]), "r"(b0), "r"(b1));
}

// ---------------- K_setup: init + dtype-detect + B-image prep ----------------
__global__ void k_setup(const int* __restrict__ ei32, int E,
                        const float* __restrict__ W, const float* __restrict__ rW, int N) {
    int i = blockIdx.x * blockDim.x + threadIdx.x;
    if (i < N) g_cnt[i] = 0;
    if (i < D) { g_sum[i] = 0.0f; g_sumsq[i] = 0.0f; }
    if (i == 0) g_is64 = 1;
    __threadfence();
    if (i < E && i < 1024) {
        if (ei32[2 * i + 1] != 0) g_is64 = 0;
    }
    if (i < 256 * 64) {
        int n = i >> 6, kw = i & 63;
        const float* src = (n < 128) ? W : rW;
        int col = (n < 128) ? n : n - 128;
        float v0 = src[(size_t)(2 * kw) * D + col];
        float v1 = src[(size_t)(2 * kw + 1) * D + col];
        float h0 = bf16_hi(v0), h1 = bf16_hi(v1);
        g_Bw_hi[n * BKW + kw] = pack2(v0, v1);
        g_Bw_lo[n * BKW + kw] = pack2(v0 - h0, v1 - h1);
        if (kw < 4) { g_Bw_hi[n * BKW + 64 + kw] = 0; g_Bw_lo[n * BKW + 64 + kw] = 0; }
    }
}

// ---------------- CSR build ----------------
__global__ void k_hist(const int* __restrict__ ei32, int E) {
    int e = blockIdx.x * blockDim.x + threadIdx.x;
    if (e >= E) return;
    int is64 = g_is64;
    atomicAdd(&g_cnt[ld_idx(ei32, (size_t)E + e, is64)], 1);
}

__global__ void __launch_bounds__(SCAN_B) k_scan1(int N) {
    __shared__ int red[SCAN_B / 32];
    int i = blockIdx.x * SCAN_B + threadIdx.x;
    int v = (i < N) ? g_cnt[i] : 0;
    #pragma unroll
    for (int o = 16; o > 0; o >>= 1) v += __shfl_down_sync(0xffffffff, v, o);
    int warp = threadIdx.x >> 5, lane = threadIdx.x & 31;
    if (lane == 0) red[warp] = v;
    __syncthreads();
    if (warp == 0) {
        int s = (lane < SCAN_B / 32) ? red[lane] : 0;
        #pragma unroll
        for (int o = 4; o > 0; o >>= 1) s += __shfl_down_sync(0xffffffff, s, o);
        if (lane == 0) g_bsum[blockIdx.x] = s;
    }
}

__global__ void __launch_bounds__(1024) k_scan2(int nblk, int N) {
    __shared__ int sh[1024];
    int t = threadIdx.x;
    int v = (t < nblk) ? g_bsum[t] : 0;
    sh[t] = v;
    __syncthreads();
    for (int off = 1; off < 1024; off <<= 1) {
        int u = (t >= off) ? sh[t - off] : 0;
        __syncthreads();
        sh[t] += u;
        __syncthreads();
    }
    if (t < nblk) g_bsum[t] = sh[t] - v;
    if (t == 0) g_roff[N] = sh[1023];
}

__global__ void __launch_bounds__(SCAN_B) k_scan3(int N) {
    __shared__ int wsum[SCAN_B / 32];
    int i = blockIdx.x * SCAN_B + threadIdx.x;
    int c = (i < N) ? g_cnt[i] : 0;
    int lane = threadIdx.x & 31, warp = threadIdx.x >> 5;
    int s = c;
    #pragma unroll
    for (int o = 1; o < 32; o <<= 1) {
        int u = __shfl_up_sync(0xffffffff, s, o);
        if (lane >= o) s += u;
    }
    if (lane == 31) wsum[warp] = s;
    __syncthreads();
    if (warp == 0) {
        int w = (lane < SCAN_B / 32) ? wsum[lane] : 0;
        #pragma unroll
        for (int o = 1; o < SCAN_B / 32; o <<= 1) {
            int u = __shfl_up_sync(0xffffffff, w, o);
            if (lane >= o) w += u;
        }
        if (lane < SCAN_B / 32) wsum[lane] = w;
    }
    __syncthreads();
    int excl = s - c + (warp > 0 ? wsum[warp - 1] : 0) + g_bsum[blockIdx.x];
    if (i < N) {
        g_roff[i] = excl;
        g_wcur[i] = excl;
        g_dinv[i] = rsqrtf((float)c + 1.0f);
    }
}

__global__ void k_fill(const int* __restrict__ ei32, int E) {
    int e = blockIdx.x * blockDim.x + threadIdx.x;
    if (e >= E) return;
    int is64 = g_is64;
    int s = ld_idx(ei32, (size_t)e, is64);
    int d = ld_idx(ei32, (size_t)E + e, is64);
    g_srcs[atomicAdd(&g_wcur[d], 1)] = s;
}

// ---------------- persistent mma.sync fused dual GEMM ----------------
// Tile: 128 rows x 256 cols; 8 warps: wr = wid&3 (32-row band, TWO m16 frags
// sharing each B load), wc = wid>>2 (128-col half). bf16x3 split, K=128.
// Writes RAW h and agg0 = b + relu(res). NO degree dependency.
#define S_BHI 0
#define S_BLO 69632
#define S_STAGE 139264          // float stage[128][136]
#define SMEM_MMA (S_STAGE + 128 * 136 * 4)

__global__ void __launch_bounds__(256, 1) k_gemm_mma(
    const float* __restrict__ x, const float* __restrict__ b,
    const float* __restrict__ rb, int N, int ntiles)
{
    extern __shared__ char smem[];
    uint32_t* sBhi = (uint32_t*)(smem + S_BHI);
    uint32_t* sBlo = (uint32_t*)(smem + S_BLO);
    float* stage = (float*)(smem + S_STAGE);

    const int tid = threadIdx.x;
    const int wid = tid >> 5, lane = tid & 31;
    const int wr = wid & 3, wc = wid >> 2;
    const int g = lane >> 2, tg = lane & 3;

    {
        const uint4* sh = (const uint4*)g_Bw_hi;
        const uint4* sl = (const uint4*)g_Bw_lo;
        uint4* dh = (uint4*)sBhi;
        uint4* dl = (uint4*)sBlo;
        #pragma unroll
        for (int i = 0; i < 17; i++) {
            int idx = tid + i * 256;
            dh[idx] = sh[idx];
            dl[idx] = sl[idx];
        }
    }
    __syncthreads();

    for (int tile = blockIdx.x; tile < ntiles; tile += gridDim.x) {
        __syncthreads();

        const int base = tile * 128 + wr * 32;
        const int rA0 = base + g,      rA1 = base + 8 + g;
        const int rB0 = base + 16 + g, rB1 = base + 24 + g;
        const bool okA0 = rA0 < N, okA1 = rA1 < N, okB0 = rB0 < N, okB1 = rB1 < N;
        const float* xA0 = x + (size_t)rA0 * D;
        const float* xA1 = x + (size_t)rA1 * D;
        const float* xB0 = x + (size_t)rB0 * D;
        const float* xB1 = x + (size_t)rB1 * D;

        float c0[16][4], c1[16][4];
        #pragma unroll
        for (int i = 0; i < 16; i++)
            #pragma unroll
            for (int j = 0; j < 4; j++) { c0[i][j] = 0.f; c1[i][j] = 0.f; }

        #pragma unroll
        for (int ks = 0; ks < 8; ks++) {
            int k0 = ks * 16 + tg * 2;
            float2 z = make_float2(0.f, 0.f);
            float2 a00 = okA0 ? *(const float2*)(xA0 + k0)     : z;
            float2 a10 = okA1 ? *(const float2*)(xA1 + k0)     : z;
            float2 a01 = okA0 ? *(const float2*)(xA0 + k0 + 8) : z;
            float2 a11 = okA1 ? *(const float2*)(xA1 + k0 + 8) : z;
            float2 b00 = okB0 ? *(const float2*)(xB0 + k0)     : z;
            float2 b10 = okB1 ? *(const float2*)(xB1 + k0)     : z;
            float2 b01 = okB0 ? *(const float2*)(xB0 + k0 + 8) : z;
            float2 b11 = okB1 ? *(const float2*)(xB1 + k0 + 8) : z;
            uint32_t ahi0[4], alo0[4], ahi1[4], alo1[4];
            ahi0[0] = pack2(a00.x, a00.y); ahi0[1] = pack2(a10.x, a10.y);
            ahi0[2] = pack2(a01.x, a01.y); ahi0[3] = pack2(a11.x, a11.y);
            alo0[0] = pack2(a00.x - bf16_hi(a00.x), a00.y - bf16_hi(a00.y));
            alo0[1] = pack2(a10.x - bf16_hi(a10.x), a10.y - bf16_hi(a10.y));
            alo0[2] = pack2(a01.x - bf16_hi(a01.x), a01.y - bf16_hi(a01.y));
            alo0[3] = pack2(a11.x - bf16_hi(a11.x), a11.y - bf16_hi(a11.y));
            ahi1[0] = pack2(b00.x, b00.y); ahi1[1] = pack2(b10.x, b10.y);
            ahi1[2] = pack2(b01.x, b01.y); ahi1[3] = pack2(b11.x, b11.y);
            alo1[0] = pack2(b00.x - bf16_hi(b00.x), b00.y - bf16_hi(b00.y));
            alo1[1] = pack2(b10.x - bf16_hi(b10.x), b10.y - bf16_hi(b10.y));
            alo1[2] = pack2(b01.x - bf16_hi(b01.x), b01.y - bf16_hi(b01.y));
            alo1[3] = pack2(b11.x - bf16_hi(b11.x), b11.y - bf16_hi(b11.y));

            #pragma unroll
            for (int nt = 0; nt < 16; nt++) {
                int nrow = wc * 128 + nt * 8 + g;
                int w0 = nrow * BKW + ks * 8 + tg;
                uint32_t b0h = sBhi[w0], b1h = sBhi[w0 + 4];
                uint32_t b0l = sBlo[w0], b1l = sBlo[w0 + 4];
                mma_bf16(c0[nt], ahi0, b0h, b1h);
                mma_bf16(c0[nt], ahi0, b0l, b1l);
                mma_bf16(c0[nt], alo0, b0h, b1h);
                mma_bf16(c1[nt], ahi1, b0h, b1h);
                mma_bf16(c1[nt], ahi1, b0l, b1l);
                mma_bf16(c1[nt], alo1, b0h, b1h);
            }
        }

        int lr = wr * 32 + g;
        if (wc == 1) {   // residual half: stage relu(val + rb)
            #pragma unroll
            for (int nt = 0; nt < 16; nt++) {
                int col = nt * 8 + tg * 2;
                float rb0 = rb[col], rb1 = rb[col + 1];
                stage[(lr)      * 136 + col]     = fmaxf(c0[nt][0] + rb0, 0.f);
                stage[(lr)      * 136 + col + 1] = fmaxf(c0[nt][1] + rb1, 0.f);
                stage[(lr + 8)  * 136 + col]     = fmaxf(c0[nt][2] + rb0, 0.f);
                stage[(lr + 8)  * 136 + col + 1] = fmaxf(c0[nt][3] + rb1, 0.f);
                stage[(lr + 16) * 136 + col]     = fmaxf(c1[nt][0] + rb0, 0.f);
                stage[(lr + 16) * 136 + col + 1] = fmaxf(c1[nt][1] + rb1, 0.f);
                stage[(lr + 24) * 136 + col]     = fmaxf(c1[nt][2] + rb0, 0.f);
                stage[(lr + 24) * 136 + col + 1] = fmaxf(c1[nt][3] + rb1, 0.f);
            }
        }
        __syncthreads();
        if (wc == 0) {   // main half: store raw h + agg0 = b + relu(res)
            #pragma unroll
            for (int nt = 0; nt < 16; nt++) {
                int col = nt * 8 + tg * 2;
                float2 bb = *(const float2*)(b + col);
                #pragma unroll
                for (int f = 0; f < 4; f++) {
                    int r = (f == 0) ? rA0 : (f == 1) ? rA1 : (f == 2) ? rB0 : rB1;
                    bool ok = (f == 0) ? okA0 : (f == 1) ? okA1 : (f == 2) ? okB0 : okB1;
                    if (!ok) continue;
                    const float* cc = (f < 2) ? c0[nt] : c1[nt];
                    float v0 = (f & 1) ? cc[2] : cc[0];
                    float v1 = (f & 1) ? cc[3] : cc[1];
                    int srow = lr + ((f & 1) ? 8 : 0) + ((f >> 1) ? 16 : 0);
                    float2 hv, ag;
                    hv.x = v0; hv.y = v1;
                    ag.x = bb.x + stage[srow * 136 + col];
                    ag.y = bb.y + stage[srow * 136 + col + 1];
                    *(float2*)(g_h   + (size_t)r * D + col) = hv;
                    *(float2*)(g_agg + (size_t)r * D + col) = ag;
                }
            }
        }
    }
}

// ---------------- CSR aggregate (incl. self-loop) + fused BN sums ----------------
__global__ void __launch_bounds__(256) k_agg(int N, int nwarps) {
    __shared__ float ss[8][128];
    __shared__ float sq[8][128];
    int wid = threadIdx.x >> 5, lane = threadIdx.x & 31;
    int gw = blockIdx.x * 8 + wid;
    float4 bs = make_float4(0.f, 0.f, 0.f, 0.f);
    float4 bq = make_float4(0.f, 0.f, 0.f, 0.f);

    for (int d = gw; d < N; d += nwarps) {
        int beg = g_roff[d], end = g_roff[d + 1];
        float di = g_dinv[d];
        // self-loop: di * h[d]
        float4 hd = *(const float4*)(g_h + (size_t)d * D + lane * 4);
        float4 acc;
        acc.x = di * hd.x; acc.y = di * hd.y; acc.z = di * hd.z; acc.w = di * hd.w;
        for (int j = beg; j < end; j++) {
            int s = g_srcs[j];
            float ds = g_dinv[s];
            float4 u = *(const float4*)(g_h + (size_t)s * D + lane * 4);
            acc.x += ds * u.x; acc.y += ds * u.y;
            acc.z += ds * u.z; acc.w += ds * u.w;
        }
        float4* ap = (float4*)(g_agg + (size_t)d * D + lane * 4);
        float4 v = *ap;
        v.x += acc.x * di; v.y += acc.y * di;
        v.z += acc.z * di; v.w += acc.w * di;
        *ap = v;
        bs.x += v.x; bs.y += v.y; bs.z += v.z; bs.w += v.w;
        bq.x += v.x * v.x; bq.y += v.y * v.y;
        bq.z += v.z * v.z; bq.w += v.w * v.w;
    }
    *(float4*)&ss[wid][lane * 4] = bs;
    *(float4*)&sq[wid][lane * 4] = bq;
    __syncthreads();
    int col = threadIdx.x & 127;
    if (threadIdx.x < 128) {
        float s = 0.f;
        #pragma unroll
        for (int w = 0; w < 8; w++) s += ss[w][col];
        atomicAdd(&g_sum[col], s);
    } else {
        float s = 0.f;
        #pragma unroll
        for (int w = 0; w < 8; w++) s += sq[w][col];
        atomicAdd(&g_sumsq[col], s);
    }
}

// ---------------- normalize (bnfin fused per-block) ----------------
__global__ void k_norm(const float* __restrict__ gamma, const float* __restrict__ beta,
                       float* __restrict__ out, int N) {
    __shared__ float ssc[128], ssh[128];
    int t = threadIdx.x;
    if (t < 128) {
        float inv_n = 1.0f / (float)N;
        float mean = g_sum[t] * inv_n;
        float var = fmaxf(g_sumsq[t] * inv_n - mean * mean, 0.0f);
        float sc = rsqrtf(var + 1e-5f) * gamma[t];
        ssc[t] = sc;
        ssh[t] = beta[t] - mean * sc;
    }
    __syncthreads();
    int idx = blockIdx.x * blockDim.x + t;
    int total = N * (D / 4);
    if (idx >= total) return;
    int colb = (idx & 31) * 4;
    float4 v = ((const float4*)g_agg)[idx];
    float4 o;
    o.x = v.x * ssc[colb]     + ssh[colb];
    o.y = v.y * ssc[colb + 1] + ssh[colb + 1];
    o.z = v.z * ssc[colb + 2] + ssh[colb + 2];
    o.w = v.w * ssc[colb + 3] + ssh[colb + 3];
    ((float4*)out)[idx] = o;
}

extern "C" void kernel_launch(void* const* d_in, const int* in_sizes, int n_in,
                              void* d_out, int out_size) {
    const float* x     = (const float*)d_in[0];
    const int*   ei32  = (const int*)d_in[1];
    const float* W     = (const float*)d_in[2];
    const float* b     = (const float*)d_in[3];
    const float* rW    = (const float*)d_in[4];
    const float* rb    = (const float*)d_in[5];
    const float* gamma = (const float*)d_in[6];
    const float* beta  = (const float*)d_in[7];
    float* out = (float*)d_out;

    int N = in_sizes[0] / D;
    int E = in_sizes[1] / 2;
    int nblk = (N + SCAN_B - 1) / SCAN_B;
    int ntiles = (N + 127) / 128;
    int gemm_grid = ntiles < 148 ? ntiles : 148;
    int agg_blocks = 1184;

    cudaFuncSetAttribute(k_gemm_mma, cudaFuncAttributeMaxDynamicSharedMemorySize, SMEM_MMA);

    cudaStream_t s2;
    cudaStreamCreateWithFlags(&s2, cudaStreamNonBlocking);
    cudaEvent_t evFork, evJoin;
    cudaEventCreateWithFlags(&evFork, cudaEventDisableTiming);
    cudaEventCreateWithFlags(&evJoin, cudaEventDisableTiming);

    // main: setup, then GEMM (depends only on setup's B images)
    k_setup<<<(N + 255) / 256, 256>>>(ei32, E, W, rW, N);

    cudaEventRecord(evFork, 0);
    cudaStreamWaitEvent(s2, evFork, 0);

    // s2: full CSR build (hist now off the critical path)
    k_hist<<<(E + 255) / 256, 256, 0, s2>>>(ei32, E);
    k_scan1<<<nblk, SCAN_B, 0, s2>>>(N);
    k_scan2<<<1, 1024, 0, s2>>>(nblk, N);
    k_scan3<<<nblk, SCAN_B, 0, s2>>>(N);
    k_fill<<<(E + 255) / 256, 256, 0, s2>>>(ei32, E);
    cudaEventRecord(evJoin, s2);

    k_gemm_mma<<<gemm_grid, 256, SMEM_MMA>>>(x, b, rb, N, ntiles);

    cudaStreamWaitEvent(0, evJoin, 0);
    k_agg<<<agg_blocks, 256>>>(N, agg_blocks * 8);
    k_norm<<<(N * (D / 4) + 255) / 256, 256>>>(gamma, beta, out, N);

    cudaEventDestroy(evFork);
    cudaEventDestroy(evJoin);
    cudaStreamDestroy(s2);
}

// round 14
// speedup vs baseline: 3.6649x; 1.0365x over previous
#include <cuda_runtime.h>
#include <cuda_bf16.h>
#include <cstdint>

#define D 128
#define MAXN 100000
#define MAXE 1000000
#define SCAN_B 256
#define MAXBLK ((MAXN + SCAN_B - 1) / SCAN_B)
#define BKW 68                 // B row stride in 32-bit words (64 data + 4 pad)
#define AGG_BLOCKS 592         // 148 SMs x 4 resident blocks (guaranteed one wave)

// ---------------- device scratch ----------------
__device__ __align__(16) float g_h[(size_t)MAXN * D];     // raw h = x@W
__device__ __align__(16) float g_agg[(size_t)MAXN * D];   // b + relu(res), then final y
__device__ __align__(16) float g_dinv[MAXN];
__device__ __align__(16) float g_sum[D];
__device__ __align__(16) float g_sumsq[D];
__device__ int g_cnt[MAXN];
__device__ int g_roff[MAXN + 1];
__device__ int g_wcur[MAXN];
__device__ int g_srcs[MAXE];
__device__ int g_bsum[MAXBLK];
__device__ int g_is64;
__device__ unsigned int g_barrier;
// B operand images: [n=256][kword=68] bf16x2 words; n<128 -> W col n, else res_W col n-128
__device__ __align__(16) uint32_t g_Bw_hi[256 * BKW];
__device__ __align__(16) uint32_t g_Bw_lo[256 * BKW];

__device__ __forceinline__ int ld_idx(const int* __restrict__ ei32, size_t pos, int is64) {
    return is64 ? ei32[pos << 1] : ei32[pos];
}
__device__ __forceinline__ uint32_t pack2(float a, float b) {
    __nv_bfloat162 t = __floats2bfloat162_rn(a, b);
    return *reinterpret_cast<uint32_t*>(&t);
}
__device__ __forceinline__ float bf16_hi(float v) {
    return __bfloat162float(__float2bfloat16(v));
}
__device__ __forceinline__ void mma_bf16(float* c, const uint32_t* a, uint32_t b0, uint32_t b1) {
    asm volatile(
        "mma.sync.aligned.m16n8k16.row.col.f32.bf16.bf16.f32 "
        "{%0,%1,%2,%3}, {%4,%5,%6,%7}, {%8,%9}, {%0,%1,%2,%3};"
        : "+f"(c[0]), "+f"(c[1]), "+f"(c[2]), "+f"(c[3])
        : "r"(a[0]), "r"(a[1]), "r"(a[2]), "r"(a[3]), "r"(b0), "r"(b1));
}

// ---------------- K_setup: init + dtype-detect + B-image prep ----------------
__global__ void k_setup(const int* __restrict__ ei32, int E,
                        const float* __restrict__ W, const float* __restrict__ rW, int N) {
    int i = blockIdx.x * blockDim.x + threadIdx.x;
    if (i < N) g_cnt[i] = 0;
    if (i < D) { g_sum[i] = 0.0f; g_sumsq[i] = 0.0f; }
    if (i == 0) { g_is64 = 1; g_barrier = 0u; }
    __threadfence();
    if (i < E && i < 1024) {
        if (ei32[2 * i + 1] != 0) g_is64 = 0;
    }
    if (i < 256 * 64) {
        int n = i >> 6, kw = i & 63;
        const float* src = (n < 128) ? W : rW;
        int col = (n < 128) ? n : n - 128;
        float v0 = src[(size_t)(2 * kw) * D + col];
        float v1 = src[(size_t)(2 * kw + 1) * D + col];
        float h0 = bf16_hi(v0), h1 = bf16_hi(v1);
        g_Bw_hi[n * BKW + kw] = pack2(v0, v1);
        g_Bw_lo[n * BKW + kw] = pack2(v0 - h0, v1 - h1);
        if (kw < 4) { g_Bw_hi[n * BKW + 64 + kw] = 0; g_Bw_lo[n * BKW + 64 + kw] = 0; }
    }
}

// ---------------- CSR build ----------------
__global__ void k_hist(const int* __restrict__ ei32, int E) {
    int e = blockIdx.x * blockDim.x + threadIdx.x;
    if (e >= E) return;
    int is64 = g_is64;
    atomicAdd(&g_cnt[ld_idx(ei32, (size_t)E + e, is64)], 1);
}

__global__ void __launch_bounds__(SCAN_B) k_scan1(int N) {
    __shared__ int red[SCAN_B / 32];
    int i = blockIdx.x * SCAN_B + threadIdx.x;
    int v = (i < N) ? g_cnt[i] : 0;
    #pragma unroll
    for (int o = 16; o > 0; o >>= 1) v += __shfl_down_sync(0xffffffff, v, o);
    int warp = threadIdx.x >> 5, lane = threadIdx.x & 31;
    if (lane == 0) red[warp] = v;
    __syncthreads();
    if (warp == 0) {
        int s = (lane < SCAN_B / 32) ? red[lane] : 0;
        #pragma unroll
        for (int o = 4; o > 0; o >>= 1) s += __shfl_down_sync(0xffffffff, s, o);
        if (lane == 0) g_bsum[blockIdx.x] = s;
    }
}

__global__ void __launch_bounds__(1024) k_scan2(int nblk, int N) {
    __shared__ int sh[1024];
    int t = threadIdx.x;
    int v = (t < nblk) ? g_bsum[t] : 0;
    sh[t] = v;
    __syncthreads();
    for (int off = 1; off < 1024; off <<= 1) {
        int u = (t >= off) ? sh[t - off] : 0;
        __syncthreads();
        sh[t] += u;
        __syncthreads();
    }
    if (t < nblk) g_bsum[t] = sh[t] - v;
    if (t == 0) g_roff[N] = sh[1023];
}

__global__ void __launch_bounds__(SCAN_B) k_scan3(int N) {
    __shared__ int wsum[SCAN_B / 32];
    int i = blockIdx.x * SCAN_B + threadIdx.x;
    int c = (i < N) ? g_cnt[i] : 0;
    int lane = threadIdx.x & 31, warp = threadIdx.x >> 5;
    int s = c;
    #pragma unroll
    for (int o = 1; o < 32; o <<= 1) {
        int u = __shfl_up_sync(0xffffffff, s, o);
        if (lane >= o) s += u;
    }
    if (lane == 31) wsum[warp] = s;
    __syncthreads();
    if (warp == 0) {
        int w = (lane < SCAN_B / 32) ? wsum[lane] : 0;
        #pragma unroll
        for (int o = 1; o < SCAN_B / 32; o <<= 1) {
            int u = __shfl_up_sync(0xffffffff, w, o);
            if (lane >= o) w += u;
        }
        if (lane < SCAN_B / 32) wsum[lane] = w;
    }
    __syncthreads();
    int excl = s - c + (warp > 0 ? wsum[warp - 1] : 0) + g_bsum[blockIdx.x];
    if (i < N) {
        g_roff[i] = excl;
        g_wcur[i] = excl;
        g_dinv[i] = rsqrtf((float)c + 1.0f);
    }
}

__global__ void k_fill(const int* __restrict__ ei32, int E) {
    int e = blockIdx.x * blockDim.x + threadIdx.x;
    if (e >= E) return;
    int is64 = g_is64;
    int s = ld_idx(ei32, (size_t)e, is64);
    int d = ld_idx(ei32, (size_t)E + e, is64);
    g_srcs[atomicAdd(&g_wcur[d], 1)] = s;
}

// ---------------- persistent mma.sync fused dual GEMM ----------------
// Tile: 128 rows x 256 cols; 8 warps: wr = wid&3 (32-row band, TWO m16 frags
// sharing each B load), wc = wid>>2 (128-col half). bf16x3 split, K=128.
// Writes RAW h and agg0 = b + relu(res). NO degree dependency.
#define S_BHI 0
#define S_BLO 69632
#define S_STAGE 139264          // float stage[128][136]
#define SMEM_MMA (S_STAGE + 128 * 136 * 4)

__global__ void __launch_bounds__(256, 1) k_gemm_mma(
    const float* __restrict__ x, const float* __restrict__ b,
    const float* __restrict__ rb, int N, int ntiles)
{
    extern __shared__ char smem[];
    uint32_t* sBhi = (uint32_t*)(smem + S_BHI);
    uint32_t* sBlo = (uint32_t*)(smem + S_BLO);
    float* stage = (float*)(smem + S_STAGE);

    const int tid = threadIdx.x;
    const int wid = tid >> 5, lane = tid & 31;
    const int wr = wid & 3, wc = wid >> 2;
    const int g = lane >> 2, tg = lane & 3;

    {
        const uint4* sh = (const uint4*)g_Bw_hi;
        const uint4* sl = (const uint4*)g_Bw_lo;
        uint4* dh = (uint4*)sBhi;
        uint4* dl = (uint4*)sBlo;
        #pragma unroll
        for (int i = 0; i < 17; i++) {
            int idx = tid + i * 256;
            dh[idx] = sh[idx];
            dl[idx] = sl[idx];
        }
    }
    __syncthreads();

    for (int tile = blockIdx.x; tile < ntiles; tile += gridDim.x) {
        __syncthreads();

        const int base = tile * 128 + wr * 32;
        const int rA0 = base + g,      rA1 = base + 8 + g;
        const int rB0 = base + 16 + g, rB1 = base + 24 + g;
        const bool okA0 = rA0 < N, okA1 = rA1 < N, okB0 = rB0 < N, okB1 = rB1 < N;
        const float* xA0 = x + (size_t)rA0 * D;
        const float* xA1 = x + (size_t)rA1 * D;
        const float* xB0 = x + (size_t)rB0 * D;
        const float* xB1 = x + (size_t)rB1 * D;

        float c0[16][4], c1[16][4];
        #pragma unroll
        for (int i = 0; i < 16; i++)
            #pragma unroll
            for (int j = 0; j < 4; j++) { c0[i][j] = 0.f; c1[i][j] = 0.f; }

        #pragma unroll
        for (int ks = 0; ks < 8; ks++) {
            int k0 = ks * 16 + tg * 2;
            float2 z = make_float2(0.f, 0.f);
            float2 a00 = okA0 ? *(const float2*)(xA0 + k0)     : z;
            float2 a10 = okA1 ? *(const float2*)(xA1 + k0)     : z;
            float2 a01 = okA0 ? *(const float2*)(xA0 + k0 + 8) : z;
            float2 a11 = okA1 ? *(const float2*)(xA1 + k0 + 8) : z;
            float2 b00 = okB0 ? *(const float2*)(xB0 + k0)     : z;
            float2 b10 = okB1 ? *(const float2*)(xB1 + k0)     : z;
            float2 b01 = okB0 ? *(const float2*)(xB0 + k0 + 8) : z;
            float2 b11 = okB1 ? *(const float2*)(xB1 + k0 + 8) : z;
            uint32_t ahi0[4], alo0[4], ahi1[4], alo1[4];
            ahi0[0] = pack2(a00.x, a00.y); ahi0[1] = pack2(a10.x, a10.y);
            ahi0[2] = pack2(a01.x, a01.y); ahi0[3] = pack2(a11.x, a11.y);
            alo0[0] = pack2(a00.x - bf16_hi(a00.x), a00.y - bf16_hi(a00.y));
            alo0[1] = pack2(a10.x - bf16_hi(a10.x), a10.y - bf16_hi(a10.y));
            alo0[2] = pack2(a01.x - bf16_hi(a01.x), a01.y - bf16_hi(a01.y));
            alo0[3] = pack2(a11.x - bf16_hi(a11.x), a11.y - bf16_hi(a11.y));
            ahi1[0] = pack2(b00.x, b00.y); ahi1[1] = pack2(b10.x, b10.y);
            ahi1[2] = pack2(b01.x, b01.y); ahi1[3] = pack2(b11.x, b11.y);
            alo1[0] = pack2(b00.x - bf16_hi(b00.x), b00.y - bf16_hi(b00.y));
            alo1[1] = pack2(b10.x - bf16_hi(b10.x), b10.y - bf16_hi(b10.y));
            alo1[2] = pack2(b01.x - bf16_hi(b01.x), b01.y - bf16_hi(b01.y));
            alo1[3] = pack2(b11.x - bf16_hi(b11.x), b11.y - bf16_hi(b11.y));

            #pragma unroll
            for (int nt = 0; nt < 16; nt++) {
                int nrow = wc * 128 + nt * 8 + g;
                int w0 = nrow * BKW + ks * 8 + tg;
                uint32_t b0h = sBhi[w0], b1h = sBhi[w0 + 4];
                uint32_t b0l = sBlo[w0], b1l = sBlo[w0 + 4];
                mma_bf16(c0[nt], ahi0, b0h, b1h);
                mma_bf16(c0[nt], ahi0, b0l, b1l);
                mma_bf16(c0[nt], alo0, b0h, b1h);
                mma_bf16(c1[nt], ahi1, b0h, b1h);
                mma_bf16(c1[nt], ahi1, b0l, b1l);
                mma_bf16(c1[nt], alo1, b0h, b1h);
            }
        }

        int lr = wr * 32 + g;
        if (wc == 1) {   // residual half: stage relu(val + rb)
            #pragma unroll
            for (int nt = 0; nt < 16; nt++) {
                int col = nt * 8 + tg * 2;
                float rb0 = rb[col], rb1 = rb[col + 1];
                stage[(lr)      * 136 + col]     = fmaxf(c0[nt][0] + rb0, 0.f);
                stage[(lr)      * 136 + col + 1] = fmaxf(c0[nt][1] + rb1, 0.f);
                stage[(lr + 8)  * 136 + col]     = fmaxf(c0[nt][2] + rb0, 0.f);
                stage[(lr + 8)  * 136 + col + 1] = fmaxf(c0[nt][3] + rb1, 0.f);
                stage[(lr + 16) * 136 + col]     = fmaxf(c1[nt][0] + rb0, 0.f);
                stage[(lr + 16) * 136 + col + 1] = fmaxf(c1[nt][1] + rb1, 0.f);
                stage[(lr + 24) * 136 + col]     = fmaxf(c1[nt][2] + rb0, 0.f);
                stage[(lr + 24) * 136 + col + 1] = fmaxf(c1[nt][3] + rb1, 0.f);
            }
        }
        __syncthreads();
        if (wc == 0) {   // main half: store raw h + agg0 = b + relu(res)
            #pragma unroll
            for (int nt = 0; nt < 16; nt++) {
                int col = nt * 8 + tg * 2;
                float2 bb = *(const float2*)(b + col);
                #pragma unroll
                for (int f = 0; f < 4; f++) {
                    int r = (f == 0) ? rA0 : (f == 1) ? rA1 : (f == 2) ? rB0 : rB1;
                    bool ok = (f == 0) ? okA0 : (f == 1) ? okA1 : (f == 2) ? okB0 : okB1;
                    if (!ok) continue;
                    const float* cc = (f < 2) ? c0[nt] : c1[nt];
                    float v0 = (f & 1) ? cc[2] : cc[0];
                    float v1 = (f & 1) ? cc[3] : cc[1];
                    int srow = lr + ((f & 1) ? 8 : 0) + ((f >> 1) ? 16 : 0);
                    float2 hv, ag;
                    hv.x = v0; hv.y = v1;
                    ag.x = bb.x + stage[srow * 136 + col];
                    ag.y = bb.y + stage[srow * 136 + col + 1];
                    *(float2*)(g_h   + (size_t)r * D + col) = hv;
                    *(float2*)(g_agg + (size_t)r * D + col) = ag;
                }
            }
        }
    }
}

// ---------------- fused: CSR aggregate + BN stats + grid-sync + normalize ----------------
// 592 blocks of 256 threads, 4 resident per SM (guaranteed single wave):
// regs capped by launch_bounds, smem 9.25KB, 1024 thr/SM.
__global__ void __launch_bounds__(256, 4) k_aggnorm(
    const float* __restrict__ gamma, const float* __restrict__ beta,
    float* __restrict__ out, int N, int nwarps)
{
    __shared__ float ss[8][128];
    __shared__ float sq[8][128];
    __shared__ float ssc[128], ssh[128];
    int wid = threadIdx.x >> 5, lane = threadIdx.x & 31;
    int gw = blockIdx.x * 8 + wid;
    float4 bs = make_float4(0.f, 0.f, 0.f, 0.f);
    float4 bq = make_float4(0.f, 0.f, 0.f, 0.f);

    for (int d = gw; d < N; d += nwarps) {
        int beg = g_roff[d], end = g_roff[d + 1];
        float di = g_dinv[d];
        float4 hd = *(const float4*)(g_h + (size_t)d * D + lane * 4);
        float4 acc;
        acc.x = di * hd.x; acc.y = di * hd.y; acc.z = di * hd.z; acc.w = di * hd.w;
        for (int j = beg; j < end; j++) {
            int s = g_srcs[j];
            float ds = g_dinv[s];
            float4 u = *(const float4*)(g_h + (size_t)s * D + lane * 4);
            acc.x += ds * u.x; acc.y += ds * u.y;
            acc.z += ds * u.z; acc.w += ds * u.w;
        }
        float4* ap = (float4*)(g_agg + (size_t)d * D + lane * 4);
        float4 v = *ap;
        v.x += acc.x * di; v.y += acc.y * di;
        v.z += acc.z * di; v.w += acc.w * di;
        *ap = v;
        bs.x += v.x; bs.y += v.y; bs.z += v.z; bs.w += v.w;
        bq.x += v.x * v.x; bq.y += v.y * v.y;
        bq.z += v.z * v.z; bq.w += v.w * v.w;
    }
    *(float4*)&ss[wid][lane * 4] = bs;
    *(float4*)&sq[wid][lane * 4] = bq;
    __syncthreads();
    int col = threadIdx.x & 127;
    if (threadIdx.x < 128) {
        float s = 0.f;
        #pragma unroll
        for (int w = 0; w < 8; w++) s += ss[w][col];
        atomicAdd(&g_sum[col], s);
    } else {
        float s = 0.f;
        #pragma unroll
        for (int w = 0; w < 8; w++) s += sq[w][col];
        atomicAdd(&g_sumsq[col], s);
    }
    __threadfence();     // make this thread's atomic + g_agg stores globally visible
    __syncthreads();

    // ---- grid barrier (all 592 blocks resident by construction) ----
    if (threadIdx.x == 0) {
        atomicAdd(&g_barrier, 1u);
        while (*((volatile unsigned int*)&g_barrier) < (unsigned int)gridDim.x) { }
    }
    __syncthreads();
    __threadfence();

    // ---- BN finalize (per block) ----
    if (threadIdx.x < 128) {
        float inv_n = 1.0f / (float)N;
        float mean = g_sum[threadIdx.x] * inv_n;
        float var = fmaxf(g_sumsq[threadIdx.x] * inv_n - mean * mean, 0.0f);
        float sc = rsqrtf(var + 1e-5f) * gamma[threadIdx.x];
        ssc[threadIdx.x] = sc;
        ssh[threadIdx.x] = beta[threadIdx.x] - mean * sc;
    }
    __syncthreads();

    // ---- normalize the same rows (L2-hot) ----
    float4 sc0 = *(const float4*)&ssc[lane * 4];
    float4 sh0 = *(const float4*)&ssh[lane * 4];
    for (int d = gw; d < N; d += nwarps) {
        float4 v = *(const float4*)(g_agg + (size_t)d * D + lane * 4);
        float4 o;
        o.x = v.x * sc0.x + sh0.x;
        o.y = v.y * sc0.y + sh0.y;
        o.z = v.z * sc0.z + sh0.z;
        o.w = v.w * sc0.w + sh0.w;
        *(float4*)(out + (size_t)d * D + lane * 4) = o;
    }
}

extern "C" void kernel_launch(void* const* d_in, const int* in_sizes, int n_in,
                              void* d_out, int out_size) {
    const float* x     = (const float*)d_in[0];
    const int*   ei32  = (const int*)d_in[1];
    const float* W     = (const float*)d_in[2];
    const float* b     = (const float*)d_in[3];
    const float* rW    = (const float*)d_in[4];
    const float* rb    = (const float*)d_in[5];
    const float* gamma = (const float*)d_in[6];
    const float* beta  = (const float*)d_in[7];
    float* out = (float*)d_out;

    int N = in_sizes[0] / D;
    int E = in_sizes[1] / 2;
    int nblk = (N + SCAN_B - 1) / SCAN_B;
    int ntiles = (N + 127) / 128;
    int gemm_grid = ntiles < 148 ? ntiles : 148;

    cudaFuncSetAttribute(k_gemm_mma, cudaFuncAttributeMaxDynamicSharedMemorySize, SMEM_MMA);

    cudaStream_t s2;
    cudaStreamCreateWithFlags(&s2, cudaStreamNonBlocking);
    cudaEvent_t evFork, evJoin;
    cudaEventCreateWithFlags(&evFork, cudaEventDisableTiming);
    cudaEventCreateWithFlags(&evJoin, cudaEventDisableTiming);

    // main: setup, then GEMM (depends only on setup's B images)
    k_setup<<<(N + 255) / 256, 256>>>(ei32, E, W, rW, N);

    cudaEventRecord(evFork, 0);
    cudaStreamWaitEvent(s2, evFork, 0);

    // s2: full CSR build (off the critical path)
    k_hist<<<(E + 255) / 256, 256, 0, s2>>>(ei32, E);
    k_scan1<<<nblk, SCAN_B, 0, s2>>>(N);
    k_scan2<<<1, 1024, 0, s2>>>(nblk, N);
    k_scan3<<<nblk, SCAN_B, 0, s2>>>(N);
    k_fill<<<(E + 255) / 256, 256, 0, s2>>>(ei32, E);
    cudaEventRecord(evJoin, s2);

    k_gemm_mma<<<gemm_grid, 256, SMEM_MMA>>>(x, b, rb, N, ntiles);

    cudaStreamWaitEvent(0, evJoin, 0);
    k_aggnorm<<<AGG_BLOCKS, 256>>>(gamma, beta, out, N, AGG_BLOCKS * 8);

    cudaEventDestroy(evFork);
    cudaEventDestroy(evJoin);
    cudaStreamDestroy(s2);
}